// round 1
// baseline (speedup 1.0000x reference)
#include <cuda_runtime.h>
#include <cuda_bf16.h>
#include <math.h>

// Problem constants
#define BATCH   4
#define S_LEN   2048
#define DMODEL  256
#define NHEADS  8
#define HD      32
#define M_ROWS  (BATCH * S_LEN)   // 8192

// Scratch (device globals: allocation-free per harness rules)
__device__ float g_Q[M_ROWS * DMODEL];
__device__ float g_K[M_ROWS * DMODEL];
__device__ float g_V[M_ROWS * DMODEL];
__device__ float g_O[M_ROWS * DMODEL];

// ---------------------------------------------------------------------------
// GEMM: C[M,256] = A[M,256] @ W[256,256]^T + bias    (W is [out,in] row-major)
// 64x64 tile, 256 threads, 4x4 micro-tile, K-chunk 16
// ---------------------------------------------------------------------------
__global__ __launch_bounds__(256) void gemm_bias_kernel(
    const float* __restrict__ A, const float* __restrict__ W,
    const float* __restrict__ bias, float* __restrict__ C)
{
    __shared__ float As[16][65];
    __shared__ float Ws[16][65];

    const int tx = threadIdx.x & 15;
    const int ty = threadIdx.x >> 4;
    const int m0 = blockIdx.y * 64;
    const int n0 = blockIdx.x * 64;

    const int lrow = threadIdx.x >> 2;        // 0..63
    const int lk4  = (threadIdx.x & 3) * 4;   // 0,4,8,12

    float c[4][4];
    #pragma unroll
    for (int i = 0; i < 4; i++)
        #pragma unroll
        for (int j = 0; j < 4; j++) c[i][j] = 0.f;

    for (int kk = 0; kk < DMODEL; kk += 16) {
        float4 av = *(const float4*)&A[(size_t)(m0 + lrow) * DMODEL + kk + lk4];
        float4 wv = *(const float4*)&W[(size_t)(n0 + lrow) * DMODEL + kk + lk4];
        As[lk4 + 0][lrow] = av.x; As[lk4 + 1][lrow] = av.y;
        As[lk4 + 2][lrow] = av.z; As[lk4 + 3][lrow] = av.w;
        Ws[lk4 + 0][lrow] = wv.x; Ws[lk4 + 1][lrow] = wv.y;
        Ws[lk4 + 2][lrow] = wv.z; Ws[lk4 + 3][lrow] = wv.w;
        __syncthreads();

        #pragma unroll
        for (int kc = 0; kc < 16; kc++) {
            float a[4], bb[4];
            #pragma unroll
            for (int i = 0; i < 4; i++) a[i]  = As[kc][ty * 4 + i];
            #pragma unroll
            for (int j = 0; j < 4; j++) bb[j] = Ws[kc][tx * 4 + j];
            #pragma unroll
            for (int i = 0; i < 4; i++)
                #pragma unroll
                for (int j = 0; j < 4; j++)
                    c[i][j] = fmaf(a[i], bb[j], c[i][j]);
        }
        __syncthreads();
    }

    #pragma unroll
    for (int i = 0; i < 4; i++) {
        const int m = m0 + ty * 4 + i;
        #pragma unroll
        for (int j = 0; j < 4; j++) {
            const int n = n0 + tx * 4 + j;
            C[(size_t)m * DMODEL + n] = c[i][j] + bias[n];
        }
    }
}

// ---------------------------------------------------------------------------
// Flash attention: 1 thread = 1 query row. BN=32 key tile staged in smem.
// Scale (1/sqrt(hd)) and log2(e) pre-folded into q; masked -> -1e30.
// ---------------------------------------------------------------------------
#define BN   32
#define ROWS 128

__global__ __launch_bounds__(128) void attn_kernel(
    const float* __restrict__ Q, const float* __restrict__ K,
    const float* __restrict__ V, const int* __restrict__ mask,
    float* __restrict__ O)
{
    __shared__ float Kt[BN][HD];
    __shared__ float Vt[BN][HD];
    __shared__ int   Mt[ROWS][BN + 1];   // +1 pad: kills 32-way bank conflict

    const int tid = threadIdx.x;
    const int b = blockIdx.z, h = blockIdx.y;
    const int r0 = blockIdx.x * ROWS;
    const int r  = r0 + tid;

    const float sc = 0.17677669529663687f * 1.4426950408889634f; // 1/sqrt(32)*log2(e)

    float q[HD];
    const float* qp = Q + ((size_t)(b * S_LEN + r)) * DMODEL + h * HD;
    #pragma unroll
    for (int d = 0; d < HD; d += 4) {
        float4 v4 = *(const float4*)&qp[d];
        q[d] = v4.x * sc; q[d + 1] = v4.y * sc;
        q[d + 2] = v4.z * sc; q[d + 3] = v4.w * sc;
    }

    float o[HD];
    #pragma unroll
    for (int d = 0; d < HD; d++) o[d] = 0.f;
    float m = -1e30f, l = 0.f;

    const int* mrow = mask + (size_t)b * S_LEN * S_LEN + (size_t)r0 * S_LEN;

    for (int k0 = 0; k0 < S_LEN; k0 += BN) {
        // Stage K/V tiles (1024 floats each) + mask tile (4096 ints), coalesced
        const float* kp = K + ((size_t)(b * S_LEN + k0)) * DMODEL + h * HD;
        const float* vp = V + ((size_t)(b * S_LEN + k0)) * DMODEL + h * HD;
        #pragma unroll
        for (int i = 0; i < 8; i++) {
            int idx = i * 128 + tid;
            int kr = idx >> 5, d = idx & 31;
            Kt[kr][d] = kp[(size_t)kr * DMODEL + d];
            Vt[kr][d] = vp[(size_t)kr * DMODEL + d];
        }
        #pragma unroll
        for (int i = 0; i < 32; i++) {
            int idx = i * 128 + tid;
            int qr = idx >> 5, kk = idx & 31;
            Mt[qr][kk] = mrow[(size_t)qr * S_LEN + k0 + kk];
        }
        __syncthreads();

        // Pass 1: scores for this tile (fully unrolled so s[] stays in regs)
        float s[BN];
        float tmax = -1e30f;
        #pragma unroll
        for (int j = 0; j < BN; j++) {
            float a0 = 0.f, a1 = 0.f, a2 = 0.f, a3 = 0.f;
            #pragma unroll
            for (int d = 0; d < HD; d += 4) {
                a0 = fmaf(q[d],     Kt[j][d],     a0);
                a1 = fmaf(q[d + 1], Kt[j][d + 1], a1);
                a2 = fmaf(q[d + 2], Kt[j][d + 2], a2);
                a3 = fmaf(q[d + 3], Kt[j][d + 3], a3);
            }
            float acc = (a0 + a1) + (a2 + a3);
            acc = (Mt[tid][j] != 0) ? acc : -1e30f;
            s[j] = acc;
            tmax = fmaxf(tmax, acc);
        }

        // Online softmax update (tile-level rescale)
        const float mnew  = fmaxf(m, tmax);
        const float scale = exp2f(m - mnew);
        l *= scale;
        #pragma unroll
        for (int d = 0; d < HD; d++) o[d] *= scale;

        #pragma unroll
        for (int j = 0; j < BN; j++) {
            float p = exp2f(s[j] - mnew);
            l += p;
            #pragma unroll
            for (int d = 0; d < HD; d++)
                o[d] = fmaf(p, Vt[j][d], o[d]);
        }
        m = mnew;
        __syncthreads();
    }

    const float inv = 1.f / l;
    float* op = O + ((size_t)(b * S_LEN + r)) * DMODEL + h * HD;
    #pragma unroll
    for (int d = 0; d < HD; d += 4) {
        float4 v4 = make_float4(o[d] * inv, o[d + 1] * inv,
                                o[d + 2] * inv, o[d + 3] * inv);
        *(float4*)&op[d] = v4;
    }
}

// ---------------------------------------------------------------------------
// Launch
// ---------------------------------------------------------------------------
extern "C" void kernel_launch(void* const* d_in, const int* in_sizes, int n_in,
                              void* d_out, int out_size)
{
    const float* query = (const float*)d_in[0];
    const float* key   = (const float*)d_in[1];
    const float* value = (const float*)d_in[2];
    const int*   mask  = (const int*)  d_in[3];
    const float* Wq = (const float*)d_in[4];
    const float* bq = (const float*)d_in[5];
    const float* Wk = (const float*)d_in[6];
    const float* bk = (const float*)d_in[7];
    const float* Wv = (const float*)d_in[8];
    const float* bv = (const float*)d_in[9];
    const float* Wo = (const float*)d_in[10];
    const float* bo = (const float*)d_in[11];
    float* out = (float*)d_out;

    float *Qb, *Kb, *Vb, *Ob;
    cudaGetSymbolAddress((void**)&Qb, g_Q);
    cudaGetSymbolAddress((void**)&Kb, g_K);
    cudaGetSymbolAddress((void**)&Vb, g_V);
    cudaGetSymbolAddress((void**)&Ob, g_O);

    dim3 gemm_grid(DMODEL / 64, M_ROWS / 64);   // (4, 128)
    gemm_bias_kernel<<<gemm_grid, 256>>>(query, Wq, bq, Qb);
    gemm_bias_kernel<<<gemm_grid, 256>>>(key,   Wk, bk, Kb);
    gemm_bias_kernel<<<gemm_grid, 256>>>(value, Wv, bv, Vb);

    dim3 attn_grid(S_LEN / ROWS, NHEADS, BATCH); // (16, 8, 4)
    attn_kernel<<<attn_grid, ROWS>>>(Qb, Kb, Vb, mask, Ob);

    gemm_bias_kernel<<<gemm_grid, 256>>>(Ob, Wo, bo, out);
}

// round 2
// speedup vs baseline: 1.0996x; 1.0996x over previous
#include <cuda_runtime.h>
#include <cuda_bf16.h>
#include <math.h>

// Problem constants
#define BATCH   4
#define S_LEN   2048
#define DMODEL  256
#define NHEADS  8
#define HD      32
#define M_ROWS  (BATCH * S_LEN)   // 8192
#define MWORDS  (S_LEN / 32)      // 64 mask words per row

// Scratch (device globals: allocation-free per harness rules)
__device__ float    g_Q[M_ROWS * DMODEL];
__device__ float    g_K[M_ROWS * DMODEL];
__device__ float    g_V[M_ROWS * DMODEL];
__device__ float    g_O[M_ROWS * DMODEL];
__device__ unsigned g_MB[BATCH * S_LEN * MWORDS];   // packed mask bits (2 MB)

// ---------------------------------------------------------------------------
// Packed f32x2 helpers (sm_103a FFMA2 path — ptxas never emits these from C++)
// ---------------------------------------------------------------------------
typedef unsigned long long u64;

__device__ __forceinline__ u64 pk2(float x, float y) {
    u64 r; asm("mov.b64 %0, {%1, %2};" : "=l"(r) : "f"(x), "f"(y)); return r;
}
__device__ __forceinline__ float2 up2(u64 r) {
    float2 f; asm("mov.b64 {%0, %1}, %2;" : "=f"(f.x), "=f"(f.y) : "l"(r)); return f;
}
__device__ __forceinline__ u64 fma2(u64 a, u64 b, u64 c) {
    u64 d; asm("fma.rn.f32x2 %0, %1, %2, %3;" : "=l"(d) : "l"(a), "l"(b), "l"(c)); return d;
}
__device__ __forceinline__ u64 mul2(u64 a, u64 b) {
    u64 d; asm("mul.rn.f32x2 %0, %1, %2;" : "=l"(d) : "l"(a), "l"(b)); return d;
}
__device__ __forceinline__ float ex2(float x) {
    float y; asm("ex2.approx.f32 %0, %1;" : "=f"(y) : "f"(x)); return y;
}

// ---------------------------------------------------------------------------
// Mask bit-pack: one ballot per warp, 67MB -> 2MB
// ---------------------------------------------------------------------------
__global__ __launch_bounds__(256) void pack_mask_kernel(
    const int* __restrict__ mask, unsigned* __restrict__ bits)
{
    int idx = blockIdx.x * 256 + threadIdx.x;
    int v = mask[idx];
    unsigned w = __ballot_sync(0xffffffffu, v != 0);
    if ((threadIdx.x & 31) == 0) bits[idx >> 5] = w;
}

// ---------------------------------------------------------------------------
// GEMM: C[M,256] = A[M,256] @ W[256,256]^T + bias  (64x64 tile, 4x4 micro)
// ---------------------------------------------------------------------------
__device__ __forceinline__ void gemm_body(
    const float* __restrict__ A, const float* __restrict__ W,
    const float* __restrict__ bias, float* __restrict__ C,
    int m0, int n0)
{
    __shared__ float As[16][65];
    __shared__ float Ws[16][65];

    const int tx = threadIdx.x & 15;
    const int ty = threadIdx.x >> 4;
    const int lrow = threadIdx.x >> 2;
    const int lk4  = (threadIdx.x & 3) * 4;

    float c[4][4];
    #pragma unroll
    for (int i = 0; i < 4; i++)
        #pragma unroll
        for (int j = 0; j < 4; j++) c[i][j] = 0.f;

    for (int kk = 0; kk < DMODEL; kk += 16) {
        float4 av = *(const float4*)&A[(size_t)(m0 + lrow) * DMODEL + kk + lk4];
        float4 wv = *(const float4*)&W[(size_t)(n0 + lrow) * DMODEL + kk + lk4];
        As[lk4 + 0][lrow] = av.x; As[lk4 + 1][lrow] = av.y;
        As[lk4 + 2][lrow] = av.z; As[lk4 + 3][lrow] = av.w;
        Ws[lk4 + 0][lrow] = wv.x; Ws[lk4 + 1][lrow] = wv.y;
        Ws[lk4 + 2][lrow] = wv.z; Ws[lk4 + 3][lrow] = wv.w;
        __syncthreads();

        #pragma unroll
        for (int kc = 0; kc < 16; kc++) {
            float a[4], bb[4];
            #pragma unroll
            for (int i = 0; i < 4; i++) a[i]  = As[kc][ty * 4 + i];
            #pragma unroll
            for (int j = 0; j < 4; j++) bb[j] = Ws[kc][tx * 4 + j];
            #pragma unroll
            for (int i = 0; i < 4; i++)
                #pragma unroll
                for (int j = 0; j < 4; j++)
                    c[i][j] = fmaf(a[i], bb[j], c[i][j]);
        }
        __syncthreads();
    }

    #pragma unroll
    for (int i = 0; i < 4; i++) {
        const int m = m0 + ty * 4 + i;
        #pragma unroll
        for (int j = 0; j < 4; j++) {
            const int n = n0 + tx * 4 + j;
            C[(size_t)m * DMODEL + n] = c[i][j] + bias[n];
        }
    }
}

// Fused Q/K/V projections: blockIdx.z selects which projection
__global__ __launch_bounds__(256) void gemm_qkv_kernel(
    const float* __restrict__ q_in, const float* __restrict__ k_in, const float* __restrict__ v_in,
    const float* __restrict__ Wq, const float* __restrict__ Wk, const float* __restrict__ Wv,
    const float* __restrict__ bq, const float* __restrict__ bk, const float* __restrict__ bv,
    float* __restrict__ Qo, float* __restrict__ Ko, float* __restrict__ Vo)
{
    const float* A; const float* W; const float* b; float* C;
    if (blockIdx.z == 0)      { A = q_in; W = Wq; b = bq; C = Qo; }
    else if (blockIdx.z == 1) { A = k_in; W = Wk; b = bk; C = Ko; }
    else                      { A = v_in; W = Wv; b = bv; C = Vo; }
    gemm_body(A, W, b, C, blockIdx.y * 64, blockIdx.x * 64);
}

__global__ __launch_bounds__(256) void gemm_bias_kernel(
    const float* __restrict__ A, const float* __restrict__ W,
    const float* __restrict__ bias, float* __restrict__ C)
{
    gemm_body(A, W, bias, C, blockIdx.y * 64, blockIdx.x * 64);
}

// ---------------------------------------------------------------------------
// Flash attention v2: 1 thread = 1 query row, packed f32x2 math, bitmask.
// 32-key staged tile, processed in two 16-key halves (s[16] registers).
// ---------------------------------------------------------------------------
#define BN   32
#define ROWS 128

__global__ __launch_bounds__(128, 3) void attn_kernel(
    const float* __restrict__ Q, const float* __restrict__ K,
    const float* __restrict__ V, const unsigned* __restrict__ mbits,
    float* __restrict__ O)
{
    __shared__ float Kt[BN][HD];
    __shared__ float Vt[BN][HD];

    const int tid = threadIdx.x;
    const int b = blockIdx.z, h = blockIdx.y;
    const int r = blockIdx.x * ROWS + tid;

    const float NINF = __int_as_float(0xff800000);  // -inf
    const float sc = 0.17677669529663687f * 1.4426950408889634f; // 1/sqrt(32)*log2(e)

    // q: 16 packed f32x2 regs, pre-scaled
    u64 q2[16];
    {
        const float* qp = Q + ((size_t)(b * S_LEN + r)) * DMODEL + h * HD;
        #pragma unroll
        for (int c = 0; c < 8; c++) {
            float4 v4 = *(const float4*)&qp[c * 4];
            q2[c * 2]     = pk2(v4.x * sc, v4.y * sc);
            q2[c * 2 + 1] = pk2(v4.z * sc, v4.w * sc);
        }
    }

    u64 o2[16];
    #pragma unroll
    for (int i = 0; i < 16; i++) o2[i] = 0ull;
    float m = -1e30f, l = 0.f;

    const unsigned* mb = mbits + (size_t)(b * S_LEN + r) * MWORDS;
    const float* kbase = K + ((size_t)b * S_LEN) * DMODEL + h * HD;
    const float* vbase = V + ((size_t)b * S_LEN) * DMODEL + h * HD;

    for (int k0 = 0; k0 < S_LEN; k0 += BN) {
        const unsigned mw = mb[k0 >> 5];   // 32 mask bits for this tile

        // Stage K/V (32 rows x 32 floats each); 2 float4 per thread per tensor
        const float* kp = kbase + (size_t)k0 * DMODEL;
        const float* vp = vbase + (size_t)k0 * DMODEL;
        #pragma unroll
        for (int i = 0; i < 2; i++) {
            int fi = i * 128 + tid;
            int row = fi >> 3, c = (fi & 7) * 4;
            *(float4*)&Kt[row][c] = *(const float4*)&kp[(size_t)row * DMODEL + c];
            *(float4*)&Vt[row][c] = *(const float4*)&vp[(size_t)row * DMODEL + c];
        }
        __syncthreads();

        #pragma unroll
        for (int half = 0; half < 2; half++) {
            const int j0 = half * 16;
            float s[16];
            float tmax = NINF;

            #pragma unroll
            for (int j = 0; j < 16; j++) {
                u64 a2 = 0ull, b2 = 0ull;
                #pragma unroll
                for (int c = 0; c < 8; c++) {
                    float4 kv = *(const float4*)&Kt[j0 + j][c * 4];
                    a2 = fma2(q2[c * 2],     pk2(kv.x, kv.y), a2);
                    b2 = fma2(q2[c * 2 + 1], pk2(kv.z, kv.w), b2);
                }
                float2 fa = up2(a2), fb = up2(b2);
                float sj = (fa.x + fa.y) + (fb.x + fb.y);
                sj = ((mw >> (j0 + j)) & 1u) ? sj : NINF;
                s[j] = sj;
                tmax = fmaxf(tmax, sj);
            }

            const float mnew = fmaxf(m, tmax);
            const float esc  = ex2(m - mnew);
            l *= esc;
            const u64 esc2 = pk2(esc, esc);
            #pragma unroll
            for (int i = 0; i < 16; i++) o2[i] = mul2(o2[i], esc2);

            #pragma unroll
            for (int j = 0; j < 16; j++) {
                const float p = ex2(s[j] - mnew);
                l += p;
                const u64 p2 = pk2(p, p);
                #pragma unroll
                for (int c = 0; c < 8; c++) {
                    float4 vv = *(const float4*)&Vt[j0 + j][c * 4];
                    o2[c * 2]     = fma2(p2, pk2(vv.x, vv.y), o2[c * 2]);
                    o2[c * 2 + 1] = fma2(p2, pk2(vv.z, vv.w), o2[c * 2 + 1]);
                }
            }
            m = mnew;
        }
        __syncthreads();
    }

    const float inv = 1.f / l;
    float* op = O + ((size_t)(b * S_LEN + r)) * DMODEL + h * HD;
    #pragma unroll
    for (int c = 0; c < 8; c++) {
        float2 fa = up2(o2[c * 2]), fb = up2(o2[c * 2 + 1]);
        float4 v4 = make_float4(fa.x * inv, fa.y * inv, fb.x * inv, fb.y * inv);
        *(float4*)&op[c * 4] = v4;
    }
}

// ---------------------------------------------------------------------------
// Launch
// ---------------------------------------------------------------------------
extern "C" void kernel_launch(void* const* d_in, const int* in_sizes, int n_in,
                              void* d_out, int out_size)
{
    const float* query = (const float*)d_in[0];
    const float* key   = (const float*)d_in[1];
    const float* value = (const float*)d_in[2];
    const int*   mask  = (const int*)  d_in[3];
    const float* Wq = (const float*)d_in[4];
    const float* bq = (const float*)d_in[5];
    const float* Wk = (const float*)d_in[6];
    const float* bk = (const float*)d_in[7];
    const float* Wv = (const float*)d_in[8];
    const float* bv = (const float*)d_in[9];
    const float* Wo = (const float*)d_in[10];
    const float* bo = (const float*)d_in[11];
    float* out = (float*)d_out;

    float *Qb, *Kb, *Vb, *Ob;
    unsigned* MBp;
    cudaGetSymbolAddress((void**)&Qb, g_Q);
    cudaGetSymbolAddress((void**)&Kb, g_K);
    cudaGetSymbolAddress((void**)&Vb, g_V);
    cudaGetSymbolAddress((void**)&Ob, g_O);
    cudaGetSymbolAddress((void**)&MBp, g_MB);

    // Pack mask bits (independent of projections)
    pack_mask_kernel<<<(BATCH * S_LEN * S_LEN) / 256, 256>>>(mask, MBp);

    // Fused Q/K/V projections
    dim3 qkv_grid(DMODEL / 64, M_ROWS / 64, 3);   // (4, 128, 3)
    gemm_qkv_kernel<<<qkv_grid, 256>>>(query, key, value,
                                       Wq, Wk, Wv, bq, bk, bv,
                                       Qb, Kb, Vb);

    dim3 attn_grid(S_LEN / ROWS, NHEADS, BATCH);  // (16, 8, 4)
    attn_kernel<<<attn_grid, ROWS>>>(Qb, Kb, Vb, MBp, Ob);

    dim3 gemm_grid(DMODEL / 64, M_ROWS / 64);
    gemm_bias_kernel<<<gemm_grid, 256>>>(Ob, Wo, bo, out);
}

// round 4
// speedup vs baseline: 2.0055x; 1.8238x over previous
#include <cuda_runtime.h>
#include <cuda_bf16.h>
#include <cstdint>
#include <math.h>

// Problem constants
#define BATCH   4
#define S_LEN   2048
#define DMODEL  256
#define NHEADS  8
#define HD      32
#define M_ROWS  (BATCH * S_LEN)   // 8192
#define MWORDS  (S_LEN / 32)      // 64 mask words per row
#define NBH     (BATCH * NHEADS)  // 32

// Scratch (device globals: allocation-free per harness rules)
__device__ float          g_Q[M_ROWS * DMODEL];
__device__ float          g_K[M_ROWS * DMODEL];
__device__ float          g_V[M_ROWS * DMODEL];
__device__ float          g_O[M_ROWS * DMODEL];
__device__ unsigned       g_MB[BATCH * S_LEN * MWORDS];        // packed mask bits
__device__ __nv_bfloat16  g_Kp[NBH * S_LEN * 64];              // [kh|kl] 128B/key, SW128 pre-swizzled
__device__ __nv_bfloat16  g_Vp[(size_t)NBH * 32 * 4096];       // per (bh,ktile): Vh^T 4KB + Vl^T 4KB pre-swizzled

// ---------------------------------------------------------------------------
// Helpers
// ---------------------------------------------------------------------------
__device__ __forceinline__ uint32_t smem_u32(const void* p) {
    uint32_t a;
    asm("{ .reg .u64 t; cvta.to.shared.u64 t, %1; cvt.u32.u64 %0, t; }" : "=r"(a) : "l"(p));
    return a;
}
__device__ __forceinline__ float ex2(float x) {
    float y; asm("ex2.approx.f32 %0, %1;" : "=f"(y) : "f"(x)); return y;
}
// pack two fp32 -> bf16x2 (lo = p0, hi = p1)
#define CVT_BF16X2(result, p0, p1) \
    asm("cvt.rn.satfinite.bf16x2.f32 %0, %1, %2;" : "=r"(result) : "f"(p1), "f"(p0))

__device__ __forceinline__ void ldm_x4(uint32_t (&r)[4], uint32_t addr) {
    asm volatile("ldmatrix.sync.aligned.m8n8.x4.shared.b16 {%0,%1,%2,%3}, [%4];"
                 : "=r"(r[0]), "=r"(r[1]), "=r"(r[2]), "=r"(r[3]) : "r"(addr));
}
__device__ __forceinline__ void mma_bf16(float (&d)[4], const uint32_t* a, const uint32_t* b) {
    asm volatile("mma.sync.aligned.m16n8k16.row.col.f32.bf16.bf16.f32 "
                 "{%0,%1,%2,%3}, {%4,%5,%6,%7}, {%8,%9}, {%0,%1,%2,%3};"
                 : "+f"(d[0]), "+f"(d[1]), "+f"(d[2]), "+f"(d[3])
                 : "r"(a[0]), "r"(a[1]), "r"(a[2]), "r"(a[3]), "r"(b[0]), "r"(b[1]));
}

#define CP16(dst, src) \
    asm volatile("cp.async.cg.shared.global [%0], [%1], 16;" :: "r"(dst), "l"(src))
#define CP_COMMIT() asm volatile("cp.async.commit_group;" ::: "memory")
#define CP_WAIT1()  asm volatile("cp.async.wait_group 1;" ::: "memory")
#define CP_WAIT0()  asm volatile("cp.async.wait_group 0;" ::: "memory")

// ---------------------------------------------------------------------------
// Mask bit-pack
// ---------------------------------------------------------------------------
__global__ __launch_bounds__(256) void pack_mask_kernel(
    const int* __restrict__ mask, unsigned* __restrict__ bits)
{
    int idx = blockIdx.x * 256 + threadIdx.x;
    unsigned w = __ballot_sync(0xffffffffu, mask[idx] != 0);
    if ((threadIdx.x & 31) == 0) bits[idx >> 5] = w;
}

// ---------------------------------------------------------------------------
// K pack: per (b,h,s): 64 bf16 = [kh[0..31] | kl[0..31]], SW128 pre-swizzled
// ---------------------------------------------------------------------------
__global__ __launch_bounds__(256) void pack_k_kernel(
    const float* __restrict__ K, __nv_bfloat16* __restrict__ Kp)
{
    int idx = blockIdx.x * 256 + threadIdx.x;      // NBH*2048*64
    int c = idx & 63;
    int row = idx >> 6;                             // bh*2048 + s
    int s = row & (S_LEN - 1);
    int bh = row >> 11;
    int b = bh >> 3, h = bh & 7;
    float v = K[(size_t)(b * S_LEN + s) * DMODEL + h * HD + (c & 31)];
    __nv_bfloat16 hi = __float2bfloat16(v);
    __nv_bfloat16 out = (c < 32) ? hi : __float2bfloat16(v - __bfloat162float(hi));
    Kp[(size_t)row * 64 + (c ^ ((s & 7) << 3))] = out;
}

// ---------------------------------------------------------------------------
// V pack: per (b,h,ktile): V^T hi image (32d x 64keys, 128B rows) then lo image
// ---------------------------------------------------------------------------
__global__ __launch_bounds__(256) void pack_v_kernel(
    const float* __restrict__ V, __nv_bfloat16* __restrict__ Vp)
{
    int idx = blockIdx.x * 256 + threadIdx.x;      // NBH*32*2*32*64
    int key = idx & 63;
    int d   = (idx >> 6) & 31;
    int img = (idx >> 11) & 1;
    int t   = (idx >> 12) & 31;
    int bh  = idx >> 17;
    int b = bh >> 3, h = bh & 7;
    float v = V[(size_t)(b * S_LEN + t * 64 + key) * DMODEL + h * HD + d];
    __nv_bfloat16 hi = __float2bfloat16(v);
    __nv_bfloat16 out = img ? __float2bfloat16(v - __bfloat162float(hi)) : hi;
    Vp[(size_t)bh * 131072 + t * 4096 + img * 2048 + d * 64 + (key ^ ((d & 7) << 3))] = out;
}

// ---------------------------------------------------------------------------
// GEMM: C[M,256] = A[M,256] @ W[256,256]^T + bias
// ---------------------------------------------------------------------------
__device__ __forceinline__ void gemm_body(
    const float* __restrict__ A, const float* __restrict__ W,
    const float* __restrict__ bias, float* __restrict__ C, int m0, int n0)
{
    __shared__ float As[16][65];
    __shared__ float Ws[16][65];
    const int tx = threadIdx.x & 15;
    const int ty = threadIdx.x >> 4;
    const int lrow = threadIdx.x >> 2;
    const int lk4  = (threadIdx.x & 3) * 4;

    float c[4][4];
    #pragma unroll
    for (int i = 0; i < 4; i++)
        #pragma unroll
        for (int j = 0; j < 4; j++) c[i][j] = 0.f;

    for (int kk = 0; kk < DMODEL; kk += 16) {
        float4 av = *(const float4*)&A[(size_t)(m0 + lrow) * DMODEL + kk + lk4];
        float4 wv = *(const float4*)&W[(size_t)(n0 + lrow) * DMODEL + kk + lk4];
        As[lk4 + 0][lrow] = av.x; As[lk4 + 1][lrow] = av.y;
        As[lk4 + 2][lrow] = av.z; As[lk4 + 3][lrow] = av.w;
        Ws[lk4 + 0][lrow] = wv.x; Ws[lk4 + 1][lrow] = wv.y;
        Ws[lk4 + 2][lrow] = wv.z; Ws[lk4 + 3][lrow] = wv.w;
        __syncthreads();
        #pragma unroll
        for (int kc = 0; kc < 16; kc++) {
            float a[4], bb[4];
            #pragma unroll
            for (int i = 0; i < 4; i++) a[i]  = As[kc][ty * 4 + i];
            #pragma unroll
            for (int j = 0; j < 4; j++) bb[j] = Ws[kc][tx * 4 + j];
            #pragma unroll
            for (int i = 0; i < 4; i++)
                #pragma unroll
                for (int j = 0; j < 4; j++)
                    c[i][j] = fmaf(a[i], bb[j], c[i][j]);
        }
        __syncthreads();
    }
    #pragma unroll
    for (int i = 0; i < 4; i++) {
        const int m = m0 + ty * 4 + i;
        #pragma unroll
        for (int j = 0; j < 4; j++) {
            const int n = n0 + tx * 4 + j;
            C[(size_t)m * DMODEL + n] = c[i][j] + bias[n];
        }
    }
}

__global__ __launch_bounds__(256) void gemm_qkv_kernel(
    const float* __restrict__ q_in, const float* __restrict__ k_in, const float* __restrict__ v_in,
    const float* __restrict__ Wq, const float* __restrict__ Wk, const float* __restrict__ Wv,
    const float* __restrict__ bq, const float* __restrict__ bk, const float* __restrict__ bv,
    float* __restrict__ Qo, float* __restrict__ Ko, float* __restrict__ Vo)
{
    const float* A; const float* W; const float* b; float* C;
    if (blockIdx.z == 0)      { A = q_in; W = Wq; b = bq; C = Qo; }
    else if (blockIdx.z == 1) { A = k_in; W = Wk; b = bk; C = Ko; }
    else                      { A = v_in; W = Wv; b = bv; C = Vo; }
    gemm_body(A, W, b, C, blockIdx.y * 64, blockIdx.x * 64);
}

__global__ __launch_bounds__(256) void gemm_bias_kernel(
    const float* __restrict__ A, const float* __restrict__ W,
    const float* __restrict__ bias, float* __restrict__ C)
{
    gemm_body(A, W, bias, C, blockIdx.y * 64, blockIdx.x * 64);
}

// ---------------------------------------------------------------------------
// mma.sync flash attention.
// CTA: 128 q rows x one (b,h); 8 warps x 16 rows; 32 key-tiles of 64.
// smem: KV double buffer [2][16KB] at 0, Q tile (128 x 128B hi|lo) at 32KB.
// ---------------------------------------------------------------------------
#define SM_KV 0
#define SM_Q  32768
#define ATTN_SMEM 49152

__global__ __launch_bounds__(256, 2) void attn_mma_kernel(
    const float* __restrict__ Q, const __nv_bfloat16* __restrict__ Kp,
    const __nv_bfloat16* __restrict__ Vp, const unsigned* __restrict__ mbits,
    float* __restrict__ O)
{
    extern __shared__ char smem[];
    const uint32_t sb = smem_u32(smem);
    const int tid = threadIdx.x;
    const int lane = tid & 31, wid = tid >> 5;
    const int b = blockIdx.z, h = blockIdx.y;
    const int q0 = blockIdx.x * 128;
    const int bh = b * NHEADS + h;
    const float SC = 0.17677669529663687f * 1.4426950408889634f; // 1/sqrt(32)*log2e

    const char* ksrc = (const char*)(Kp + (size_t)bh * 131072);
    const char* vsrc = (const char*)(Vp + (size_t)bh * 131072);

    // ---- prefetch tile 0 ----
    {
        uint32_t d0 = sb + SM_KV;
        CP16(d0 + tid * 16,                ksrc + tid * 16);
        CP16(d0 + (tid + 256) * 16,        ksrc + (tid + 256) * 16);
        CP16(d0 + 8192 + tid * 16,         vsrc + tid * 16);
        CP16(d0 + 8192 + (tid + 256) * 16, vsrc + (tid + 256) * 16);
        CP_COMMIT();
    }

    // ---- Q staging: row = tid>>1, dim half = (tid&1)*16; bf16 hi/lo, swizzled ----
    {
        const int m = tid >> 1;
        const int dh = (tid & 1) * 16;
        const float* qp = Q + ((size_t)(b * S_LEN + q0 + m)) * DMODEL + h * HD + dh;
        const uint32_t qrow = sb + SM_Q + m * 128;
        const int sw = (m & 7);
        #pragma unroll
        for (int c4 = 0; c4 < 2; c4++) {   // 2 x float4-pairs => 4 u32 hi + 4 lo per c4? (process 8 dims)
            // process 8 dims per c4 iteration: two float4
            #pragma unroll
            for (int half = 0; half < 2; half++) {
                float4 v4 = *(const float4*)&qp[c4 * 8 + half * 4];
                float f0 = v4.x * SC, f1 = v4.y * SC, f2 = v4.z * SC, f3 = v4.w * SC;
                uint32_t hp0, hp1, lp0, lp1;
                CVT_BF16X2(hp0, f0, f1);
                CVT_BF16X2(hp1, f2, f3);
                float h0 = __uint_as_float(hp0 << 16), h1 = __uint_as_float(hp0 & 0xffff0000u);
                float h2 = __uint_as_float(hp1 << 16), h3 = __uint_as_float(hp1 & 0xffff0000u);
                CVT_BF16X2(lp0, f0 - h0, f1 - h1);
                CVT_BF16X2(lp1, f2 - h2, f3 - h3);
                // global u32 index: i = (tid&1)*8 + c4*4 + half*2 + {0,1}
                int i0 = (tid & 1) * 8 + c4 * 4 + half * 2;
                #pragma unroll
                for (int u = 0; u < 2; u++) {
                    int i = i0 + u;
                    uint32_t hv = u ? hp1 : hp0;
                    uint32_t lv = u ? lp1 : lp0;
                    int chih = (i >> 2);
                    int chil = 4 + (i >> 2);
                    *(uint32_t*)(smem + (qrow - sb) + (((chih ^ sw)) << 4) + (i & 3) * 4) = hv;
                    *(uint32_t*)(smem + (qrow - sb) + (((chil ^ sw)) << 4) + (i & 3) * 4) = lv;
                }
            }
        }
    }
    __syncthreads();

    // ---- load Q A-fragments (per warp: rows wid*16..+15, K=32, hi+lo) ----
    uint32_t qfh[2][4], qfl[2][4];
    {
        const int m_off = (lane & 7) + ((lane >> 3) & 1) * 8;
        const int coff  = (lane >> 4) & 1;
        const int m = wid * 16 + m_off;
        const uint32_t qrow = sb + SM_Q + m * 128;
        #pragma unroll
        for (int k16 = 0; k16 < 2; k16++) {
            int ch = 2 * k16 + coff;
            ldm_x4(qfh[k16], qrow + (((ch ^ (m & 7))) << 4));
            int cl = ch + 4;
            ldm_x4(qfl[k16], qrow + (((cl ^ (m & 7))) << 4));
        }
    }

    // lane-derived B-operand address components
    const int kb_row = (lane & 7) + ((lane >> 4) & 1) * 8;
    const int kb_c   = (lane >> 3) & 1;

    // mask row pointers (rows r0 = wid*16 + lane/4, r1 = r0 + 8)
    const unsigned* mb0 = mbits + (size_t)(b * S_LEN + q0 + wid * 16 + (lane >> 2)) * MWORDS;
    const unsigned* mb1 = mb0 + 8 * MWORDS;

    float l0 = 0.f, l1 = 0.f;
    float o[4][4];
    #pragma unroll
    for (int i = 0; i < 4; i++)
        #pragma unroll
        for (int j = 0; j < 4; j++) o[i][j] = 0.f;

    for (int t = 0; t < 32; t++) {
        // prefetch t+1, wait for t
        if (t < 31) {
            uint32_t d1 = sb + SM_KV + ((t + 1) & 1) * 16384;
            const char* ks = ksrc + (size_t)(t + 1) * 8192;
            const char* vs = vsrc + (size_t)(t + 1) * 8192;
            CP16(d1 + tid * 16,                ks + tid * 16);
            CP16(d1 + (tid + 256) * 16,        ks + (tid + 256) * 16);
            CP16(d1 + 8192 + tid * 16,         vs + tid * 16);
            CP16(d1 + 8192 + (tid + 256) * 16, vs + (tid + 256) * 16);
            CP_COMMIT();
            CP_WAIT1();
        } else {
            CP_WAIT0();
        }
        __syncthreads();

        const uint32_t kbase = sb + SM_KV + (t & 1) * 16384;
        const uint32_t vbase = kbase + 8192;

        // ---- QK^T: S(16x64) = qh*kh + ql*kh + qh*kl ----
        float c[8][4];
        #pragma unroll
        for (int i = 0; i < 8; i++)
            #pragma unroll
            for (int j = 0; j < 4; j++) c[i][j] = 0.f;

        #pragma unroll
        for (int k16 = 0; k16 < 2; k16++) {
            #pragma unroll
            for (int np = 0; np < 4; np++) {
                const int key = np * 16 + kb_row;
                const int ch  = 2 * k16 + kb_c;           // Kh chunks 0..3
                uint32_t bhf[4], blf[4];
                ldm_x4(bhf, kbase + key * 128 + (((ch ^ (key & 7))) << 4));
                mma_bf16(c[2 * np],     qfh[k16], bhf + 0);
                mma_bf16(c[2 * np + 1], qfh[k16], bhf + 2);
                mma_bf16(c[2 * np],     qfl[k16], bhf + 0);
                mma_bf16(c[2 * np + 1], qfl[k16], bhf + 2);
                const int cl = ch + 4;                     // Kl chunks 4..7
                ldm_x4(blf, kbase + key * 128 + (((cl ^ (key & 7))) << 4));
                mma_bf16(c[2 * np],     qfh[k16], blf + 0);
                mma_bf16(c[2 * np + 1], qfh[k16], blf + 2);
            }
        }

        // ---- softmax: p = exp2(s) or 0; build P hi/lo A-fragments ----
        const uint64_t mw0 = *(const uint64_t*)(mb0 + t * 2);
        const uint64_t mw1 = *(const uint64_t*)(mb1 + t * 2);
        uint32_t aph[4][4], apl[4][4];
        #pragma unroll
        for (int jj = 0; jj < 4; jj++) {
            #pragma unroll
            for (int half = 0; half < 2; half++) {
                const int j = 2 * jj + half;
                const int colb = j * 8 + (lane & 3) * 2;
                float p0 = ((mw0 >> colb)       & 1) ? ex2(c[j][0]) : 0.f;
                float p1 = ((mw0 >> (colb + 1)) & 1) ? ex2(c[j][1]) : 0.f;
                float p2 = ((mw1 >> colb)       & 1) ? ex2(c[j][2]) : 0.f;
                float p3 = ((mw1 >> (colb + 1)) & 1) ? ex2(c[j][3]) : 0.f;
                l0 += p0 + p1; l1 += p2 + p3;
                uint32_t hp01, hp23;
                CVT_BF16X2(hp01, p0, p1);
                CVT_BF16X2(hp23, p2, p3);
                float r0 = p0 - __uint_as_float(hp01 << 16);
                float r1 = p1 - __uint_as_float(hp01 & 0xffff0000u);
                float r2 = p2 - __uint_as_float(hp23 << 16);
                float r3 = p3 - __uint_as_float(hp23 & 0xffff0000u);
                uint32_t lp01, lp23;
                CVT_BF16X2(lp01, r0, r1);
                CVT_BF16X2(lp23, r2, r3);
                aph[jj][half * 2]     = hp01;
                aph[jj][half * 2 + 1] = hp23;
                apl[jj][half * 2]     = lp01;
                apl[jj][half * 2 + 1] = lp23;
            }
        }

        // ---- PV: O(16x32) += ph*vh + pl*vh + ph*vl ----
        #pragma unroll
        for (int k16 = 0; k16 < 4; k16++) {
            #pragma unroll
            for (int np = 0; np < 2; np++) {
                const int d  = np * 16 + kb_row;          // out-dim row of V^T
                const int ch = 2 * k16 + kb_c;            // key chunk 0..7
                const uint32_t swo = (((ch ^ (d & 7))) << 4);
                uint32_t bvh[4], bvl[4];
                ldm_x4(bvh, vbase + d * 128 + swo);
                mma_bf16(o[2 * np],     aph[k16], bvh + 0);
                mma_bf16(o[2 * np + 1], aph[k16], bvh + 2);
                mma_bf16(o[2 * np],     apl[k16], bvh + 0);
                mma_bf16(o[2 * np + 1], apl[k16], bvh + 2);
                ldm_x4(bvl, vbase + 4096 + d * 128 + swo);
                mma_bf16(o[2 * np],     aph[k16], bvl + 0);
                mma_bf16(o[2 * np + 1], aph[k16], bvl + 2);
            }
        }
        __syncthreads();
    }

    // ---- finalize: reduce l across the 4 lanes sharing each row, store ----
    l0 += __shfl_xor_sync(0xffffffffu, l0, 1);
    l0 += __shfl_xor_sync(0xffffffffu, l0, 2);
    l1 += __shfl_xor_sync(0xffffffffu, l1, 1);
    l1 += __shfl_xor_sync(0xffffffffu, l1, 2);
    const float inv0 = 1.f / l0, inv1 = 1.f / l1;

    const int r0g = q0 + wid * 16 + (lane >> 2);
    float* orow0 = g_O + (size_t)(b * S_LEN + r0g) * DMODEL + h * HD + (lane & 3) * 2;
    float* orow1 = orow0 + 8 * DMODEL;
    #pragma unroll
    for (int j = 0; j < 4; j++) {
        *(float2*)(orow0 + j * 8) = make_float2(o[j][0] * inv0, o[j][1] * inv0);
        *(float2*)(orow1 + j * 8) = make_float2(o[j][2] * inv1, o[j][3] * inv1);
    }
}

// ---------------------------------------------------------------------------
// Launch
// ---------------------------------------------------------------------------
extern "C" void kernel_launch(void* const* d_in, const int* in_sizes, int n_in,
                              void* d_out, int out_size)
{
    const float* query = (const float*)d_in[0];
    const float* key   = (const float*)d_in[1];
    const float* value = (const float*)d_in[2];
    const int*   mask  = (const int*)  d_in[3];
    const float* Wq = (const float*)d_in[4];
    const float* bq = (const float*)d_in[5];
    const float* Wk = (const float*)d_in[6];
    const float* bk = (const float*)d_in[7];
    const float* Wv = (const float*)d_in[8];
    const float* bv = (const float*)d_in[9];
    const float* Wo = (const float*)d_in[10];
    const float* bo = (const float*)d_in[11];
    float* out = (float*)d_out;

    float *Qb, *Kb, *Vb, *Ob;
    unsigned* MBp;
    __nv_bfloat16 *Kpp, *Vpp;
    cudaGetSymbolAddress((void**)&Qb, g_Q);
    cudaGetSymbolAddress((void**)&Kb, g_K);
    cudaGetSymbolAddress((void**)&Vb, g_V);
    cudaGetSymbolAddress((void**)&Ob, g_O);
    cudaGetSymbolAddress((void**)&MBp, g_MB);
    cudaGetSymbolAddress((void**)&Kpp, g_Kp);
    cudaGetSymbolAddress((void**)&Vpp, g_Vp);

    cudaFuncSetAttribute(attn_mma_kernel, cudaFuncAttributeMaxDynamicSharedMemorySize, ATTN_SMEM);

    pack_mask_kernel<<<(BATCH * S_LEN * S_LEN) / 256, 256>>>(mask, MBp);

    dim3 qkv_grid(DMODEL / 64, M_ROWS / 64, 3);
    gemm_qkv_kernel<<<qkv_grid, 256>>>(query, key, value,
                                       Wq, Wk, Wv, bq, bk, bv, Qb, Kb, Vb);

    pack_k_kernel<<<(NBH * S_LEN * 64) / 256, 256>>>(Kb, Kpp);
    pack_v_kernel<<<(NBH * 32 * 4096) / 256, 256>>>(Vb, Vpp);

    dim3 attn_grid(S_LEN / 128, NHEADS, BATCH);   // (16, 8, 4)
    attn_mma_kernel<<<attn_grid, 256, ATTN_SMEM>>>(Qb, Kpp, Vpp, MBp, Ob);

    dim3 gemm_grid(DMODEL / 64, M_ROWS / 64);
    gemm_bias_kernel<<<gemm_grid, 256>>>(Ob, Wo, bo, out);
}

// round 10
// speedup vs baseline: 2.5823x; 1.2876x over previous
#include <cuda_runtime.h>
#include <cuda_bf16.h>
#include <cstdint>
#include <math.h>

// Problem constants
#define BATCH   4
#define S_LEN   2048
#define DMODEL  256
#define NHEADS  8
#define HD      32
#define M_ROWS  (BATCH * S_LEN)   // 8192
#define MWORDS  (S_LEN / 32)      // 64 mask words per row
#define NBH     (BATCH * NHEADS)  // 32

// Scratch (device globals: allocation-free per harness rules)
__device__ float          g_Q[M_ROWS * DMODEL];
__device__ float          g_K[M_ROWS * DMODEL];
__device__ float          g_V[M_ROWS * DMODEL];
__device__ unsigned       g_MB[BATCH * S_LEN * MWORDS];        // packed mask bits
__device__ __nv_bfloat16  g_Kp[NBH * S_LEN * 64];              // attn K tiles, SW128 pre-swizzled
__device__ __nv_bfloat16  g_Vp[(size_t)NBH * 32 * 4096];       // attn V^T tiles pre-swizzled
// GEMM operand packs: A-format [blk 0..7][row][64 bf16], SW128 swizzled per row
__device__ __nv_bfloat16  g_Aq[(size_t)8 * M_ROWS * 64];
__device__ __nv_bfloat16  g_Ak[(size_t)8 * M_ROWS * 64];
__device__ __nv_bfloat16  g_Av[(size_t)8 * M_ROWS * 64];
__device__ __nv_bfloat16  g_Op[(size_t)8 * M_ROWS * 64];       // attn output, packed directly
__device__ __nv_bfloat16  g_Wp[(size_t)4 * 8 * 256 * 64];      // weights q,k,v,o

// ---------------------------------------------------------------------------
// Helpers
// ---------------------------------------------------------------------------
__device__ __forceinline__ uint32_t smem_u32(const void* p) {
    uint32_t a;
    asm("{ .reg .u64 t; cvta.to.shared.u64 t, %1; cvt.u32.u64 %0, t; }" : "=r"(a) : "l"(p));
    return a;
}
__device__ __forceinline__ float ex2(float x) {
    float y; asm("ex2.approx.f32 %0, %1;" : "=f"(y) : "f"(x)); return y;
}
// pack two fp32 -> bf16x2 (lo = p0, hi = p1)
#define CVT_BF16X2(result, p0, p1) \
    asm("cvt.rn.satfinite.bf16x2.f32 %0, %1, %2;" : "=r"(result) : "f"(p1), "f"(p0))

__device__ __forceinline__ void ldm_x4(uint32_t (&r)[4], uint32_t addr) {
    asm volatile("ldmatrix.sync.aligned.m8n8.x4.shared.b16 {%0,%1,%2,%3}, [%4];"
                 : "=r"(r[0]), "=r"(r[1]), "=r"(r[2]), "=r"(r[3]) : "r"(addr));
}
__device__ __forceinline__ void mma_bf16(float (&d)[4], const uint32_t* a, const uint32_t* b) {
    asm volatile("mma.sync.aligned.m16n8k16.row.col.f32.bf16.bf16.f32 "
                 "{%0,%1,%2,%3}, {%4,%5,%6,%7}, {%8,%9}, {%0,%1,%2,%3};"
                 : "+f"(d[0]), "+f"(d[1]), "+f"(d[2]), "+f"(d[3])
                 : "r"(a[0]), "r"(a[1]), "r"(a[2]), "r"(a[3]), "r"(b[0]), "r"(b[1]));
}

#define CP16(dst, src) \
    asm volatile("cp.async.cg.shared.global [%0], [%1], 16;" :: "r"(dst), "l"(src))
#define CP_COMMIT() asm volatile("cp.async.commit_group;" ::: "memory")
#define CP_WAIT1()  asm volatile("cp.async.wait_group 1;" ::: "memory")
#define CP_WAIT0()  asm volatile("cp.async.wait_group 0;" ::: "memory")

// ---------------------------------------------------------------------------
// Mask bit-pack
// ---------------------------------------------------------------------------
__global__ __launch_bounds__(256) void pack_mask_kernel(
    const int* __restrict__ mask, unsigned* __restrict__ bits)
{
    int idx = blockIdx.x * 256 + threadIdx.x;
    unsigned w = __ballot_sync(0xffffffffu, mask[idx] != 0);
    if ((threadIdx.x & 31) == 0) bits[idx >> 5] = w;
}

// ---------------------------------------------------------------------------
// Pack activations (q/k/v inputs) into GEMM A-format: [blk][m][64], swizzled
// ---------------------------------------------------------------------------
__global__ __launch_bounds__(256) void pack_a3_kernel(
    const float* __restrict__ q, const float* __restrict__ k, const float* __restrict__ v,
    __nv_bfloat16* __restrict__ Aq, __nv_bfloat16* __restrict__ Ak, __nv_bfloat16* __restrict__ Av)
{
    const float* src; __nv_bfloat16* dst;
    if (blockIdx.y == 0)      { src = q; dst = Aq; }
    else if (blockIdx.y == 1) { src = k; dst = Ak; }
    else                      { src = v; dst = Av; }
    int idx = blockIdx.x * 256 + threadIdx.x;     // 8 * 8192 * 64
    int c   = idx & 63;
    int m   = (idx >> 6) & (M_ROWS - 1);
    int blk = idx >> 19;
    int d = blk * 32 + (c & 31);
    float val = src[(size_t)m * DMODEL + d];
    __nv_bfloat16 hi = __float2bfloat16(val);
    __nv_bfloat16 out = (c < 32) ? hi : __float2bfloat16(val - __bfloat162float(hi));
    dst[(((size_t)blk * M_ROWS + m) << 6) + (c ^ ((m & 7) << 3))] = out;
}

// ---------------------------------------------------------------------------
// Pack all 4 weight matrices: [w][blk][n][64], swizzled
// ---------------------------------------------------------------------------
__global__ __launch_bounds__(256) void pack_w_kernel(
    const float* __restrict__ Wq, const float* __restrict__ Wk,
    const float* __restrict__ Wv, const float* __restrict__ Wo,
    __nv_bfloat16* __restrict__ Wp)
{
    int idx = blockIdx.x * 256 + threadIdx.x;     // 4 * 8 * 256 * 64
    int c   = idx & 63;
    int n   = (idx >> 6) & 255;
    int blk = (idx >> 14) & 7;
    int w   = idx >> 17;
    const float* W = (w == 0) ? Wq : (w == 1) ? Wk : (w == 2) ? Wv : Wo;
    int d = blk * 32 + (c & 31);
    float val = W[(size_t)n * DMODEL + d];
    __nv_bfloat16 hi = __float2bfloat16(val);
    __nv_bfloat16 out = (c < 32) ? hi : __float2bfloat16(val - __bfloat162float(hi));
    Wp[(((size_t)(w * 8 + blk) * 256 + n) << 6) + (c ^ ((n & 7) << 3))] = out;
}

// ---------------------------------------------------------------------------
// K pack for attention: per (b,h,s): 64 bf16 = [kh|kl], SW128 pre-swizzled
// ---------------------------------------------------------------------------
__global__ __launch_bounds__(256) void pack_k_kernel(
    const float* __restrict__ K, __nv_bfloat16* __restrict__ Kp)
{
    int idx = blockIdx.x * 256 + threadIdx.x;      // NBH*2048*64
    int c = idx & 63;
    int row = idx >> 6;
    int s = row & (S_LEN - 1);
    int bh = row >> 11;
    int b = bh >> 3, h = bh & 7;
    float v = K[(size_t)(b * S_LEN + s) * DMODEL + h * HD + (c & 31)];
    __nv_bfloat16 hi = __float2bfloat16(v);
    __nv_bfloat16 out = (c < 32) ? hi : __float2bfloat16(v - __bfloat162float(hi));
    Kp[(size_t)row * 64 + (c ^ ((s & 7) << 3))] = out;
}

// ---------------------------------------------------------------------------
// V pack for attention: per (b,h,ktile): V^T hi image then lo image, swizzled
// ---------------------------------------------------------------------------
__global__ __launch_bounds__(256) void pack_v_kernel(
    const float* __restrict__ V, __nv_bfloat16* __restrict__ Vp)
{
    int idx = blockIdx.x * 256 + threadIdx.x;      // NBH*32*2*32*64
    int key = idx & 63;
    int d   = (idx >> 6) & 31;
    int img = (idx >> 11) & 1;
    int t   = (idx >> 12) & 31;
    int bh  = idx >> 17;
    int b = bh >> 3, h = bh & 7;
    float v = V[(size_t)(b * S_LEN + t * 64 + key) * DMODEL + h * HD + d];
    __nv_bfloat16 hi = __float2bfloat16(v);
    __nv_bfloat16 out = img ? __float2bfloat16(v - __bfloat162float(hi)) : hi;
    Vp[(size_t)bh * 131072 + t * 4096 + img * 2048 + d * 64 + (key ^ ((d & 7) << 3))] = out;
}

// ---------------------------------------------------------------------------
// Tensor-core GEMM: C[M,256] = A[M,256] @ W^T + bias, bf16 hi/lo 3-term.
// ---------------------------------------------------------------------------
#define GEMM_SMEM 98304

__device__ __forceinline__ void gemm_tc_body(
    const __nv_bfloat16* __restrict__ Ap, const __nv_bfloat16* __restrict__ Wp,
    const float* __restrict__ bias, float* __restrict__ C, char* smem)
{
    const uint32_t sb = smem_u32(smem);
    const int tid = threadIdx.x, lane = tid & 31, wid = tid >> 5;
    const int n0 = blockIdx.x * 64, m0 = blockIdx.y * 128;
    const char* Ab = (const char*)Ap;
    const char* Wb = (const char*)Wp;

    auto stage = [&](int t, uint32_t buf) {
        #pragma unroll
        for (int i = 0; i < 8; i++) {
            int g = i * 256 + tid;
            int blk = g >> 10, row = (g >> 3) & 127, ch = g & 7;
            CP16(sb + buf + blk * 16384 + row * 128 + ch * 16,
                 Ab + ((size_t)(t * 2 + blk) * M_ROWS + m0 + row) * 128 + ch * 16);
        }
        #pragma unroll
        for (int i = 0; i < 4; i++) {
            int g = i * 256 + tid;
            int blk = g >> 9, row = (g >> 3) & 63, ch = g & 7;
            CP16(sb + buf + 32768 + blk * 8192 + row * 128 + ch * 16,
                 Wb + ((size_t)(t * 2 + blk) * 256 + n0 + row) * 128 + ch * 16);
        }
        CP_COMMIT();
    };

    stage(0, 0);

    float c[8][4];
    #pragma unroll
    for (int i = 0; i < 8; i++)
        #pragma unroll
        for (int j = 0; j < 4; j++) c[i][j] = 0.f;

    const int m_off = (lane & 7) + ((lane >> 3) & 1) * 8;
    const int coff  = (lane >> 4) & 1;
    const int m = wid * 16 + m_off;
    const int kb_row = (lane & 7) + ((lane >> 4) & 1) * 8;
    const int kb_c   = (lane >> 3) & 1;

    for (int t = 0; t < 4; t++) {
        if (t < 3) { stage(t + 1, ((t + 1) & 1) * 49152); CP_WAIT1(); }
        else       { CP_WAIT0(); }
        __syncthreads();

        const uint32_t abase = sb + (t & 1) * 49152;
        const uint32_t wbase = abase + 32768;

        #pragma unroll
        for (int k16 = 0; k16 < 4; k16++) {
            const int ablk = k16 >> 1;
            const int ch = 2 * (k16 & 1) + coff;
            const uint32_t arow = abase + ablk * 16384 + m * 128;
            uint32_t afh[4], afl[4];
            ldm_x4(afh, arow + (((ch)     ^ (m & 7)) << 4));
            ldm_x4(afl, arow + (((ch + 4) ^ (m & 7)) << 4));
            #pragma unroll
            for (int np = 0; np < 4; np++) {
                const int n = np * 16 + kb_row;
                const uint32_t wrow = wbase + ablk * 8192 + n * 128;
                const int wch = 2 * (k16 & 1) + kb_c;
                uint32_t bhf[4], blf[4];
                ldm_x4(bhf, wrow + (((wch)     ^ (n & 7)) << 4));
                mma_bf16(c[2 * np],     afh, bhf + 0);
                mma_bf16(c[2 * np + 1], afh, bhf + 2);
                mma_bf16(c[2 * np],     afl, bhf + 0);
                mma_bf16(c[2 * np + 1], afl, bhf + 2);
                ldm_x4(blf, wrow + (((wch + 4) ^ (n & 7)) << 4));
                mma_bf16(c[2 * np],     afh, blf + 0);
                mma_bf16(c[2 * np + 1], afh, blf + 2);
            }
        }
        __syncthreads();
    }

    const int r0 = m0 + wid * 16 + (lane >> 2);
    #pragma unroll
    for (int np = 0; np < 4; np++) {
        #pragma unroll
        for (int half = 0; half < 2; half++) {
            const int col = n0 + np * 16 + half * 8 + (lane & 3) * 2;
            const float b0 = bias[col], b1 = bias[col + 1];
            float* p0 = C + (size_t)r0 * DMODEL + col;
            *(float2*)p0 = make_float2(c[2 * np + half][0] + b0, c[2 * np + half][1] + b1);
            *(float2*)(p0 + 8 * DMODEL) = make_float2(c[2 * np + half][2] + b0, c[2 * np + half][3] + b1);
        }
    }
}

__global__ __launch_bounds__(256, 2) void gemm_tc_qkv(
    const __nv_bfloat16* __restrict__ Aq, const __nv_bfloat16* __restrict__ Ak,
    const __nv_bfloat16* __restrict__ Av, const __nv_bfloat16* __restrict__ Wp,
    const float* __restrict__ bq, const float* __restrict__ bk, const float* __restrict__ bv,
    float* __restrict__ Qo, float* __restrict__ Ko, float* __restrict__ Vo)
{
    extern __shared__ char smem[];
    const __nv_bfloat16* A; const __nv_bfloat16* W; const float* b; float* C;
    if (blockIdx.z == 0)      { A = Aq; W = Wp;                       b = bq; C = Qo; }
    else if (blockIdx.z == 1) { A = Ak; W = Wp + (size_t)1 * 131072;  b = bk; C = Ko; }
    else                      { A = Av; W = Wp + (size_t)2 * 131072;  b = bv; C = Vo; }
    gemm_tc_body(A, W, b, C, smem);
}

__global__ __launch_bounds__(256, 2) void gemm_tc_one(
    const __nv_bfloat16* __restrict__ Ap, const __nv_bfloat16* __restrict__ Wp,
    const float* __restrict__ bias, float* __restrict__ C)
{
    extern __shared__ char smem[];
    gemm_tc_body(Ap, Wp, bias, C, smem);
}

// ---------------------------------------------------------------------------
// mma.sync flash attention; epilogue writes packed bf16 hi/lo GEMM-A format
// directly into g_Op (blk == head since HD==32).
// FIX vs R5-R9: V-lo ldmatrix uses chunk ch (separate full image at +4096),
// NOT ch+4 (that encoding is only valid for K's shared-row layout).
// ---------------------------------------------------------------------------
#define SM_KV 0
#define SM_Q  32768
#define ATTN_SMEM 49152

__global__ __launch_bounds__(256, 2) void attn_mma_kernel(
    const float* __restrict__ Q, const __nv_bfloat16* __restrict__ Kp,
    const __nv_bfloat16* __restrict__ Vp, const unsigned* __restrict__ mbits)
{
    extern __shared__ char smem[];
    const uint32_t sb = smem_u32(smem);
    const int tid = threadIdx.x;
    const int lane = tid & 31, wid = tid >> 5;
    const int b = blockIdx.z, h = blockIdx.y;
    const int q0 = blockIdx.x * 128;
    const int bh = b * NHEADS + h;
    const float SC = 0.17677669529663687f * 1.4426950408889634f; // 1/sqrt(32)*log2e

    const char* ksrc = (const char*)(Kp + (size_t)bh * 131072);
    const char* vsrc = (const char*)(Vp + (size_t)bh * 131072);

    // ---- prefetch tile 0 ----
    {
        uint32_t d0 = sb + SM_KV;
        CP16(d0 + tid * 16,                ksrc + tid * 16);
        CP16(d0 + (tid + 256) * 16,        ksrc + (tid + 256) * 16);
        CP16(d0 + 8192 + tid * 16,         vsrc + tid * 16);
        CP16(d0 + 8192 + (tid + 256) * 16, vsrc + (tid + 256) * 16);
        CP_COMMIT();
    }

    // ---- Q staging: bf16 hi/lo, swizzled ----
    {
        const int m = tid >> 1;
        const float* qp = Q + ((size_t)(b * S_LEN + q0 + m)) * DMODEL + h * HD + (tid & 1) * 16;
        const int sw = (m & 7);
        #pragma unroll
        for (int c4 = 0; c4 < 2; c4++) {
            #pragma unroll
            for (int half = 0; half < 2; half++) {
                float4 v4 = *(const float4*)&qp[c4 * 8 + half * 4];
                float f0 = v4.x * SC, f1 = v4.y * SC, f2 = v4.z * SC, f3 = v4.w * SC;
                uint32_t hp0, hp1, lp0, lp1;
                CVT_BF16X2(hp0, f0, f1);
                CVT_BF16X2(hp1, f2, f3);
                float h0 = __uint_as_float(hp0 << 16), h1 = __uint_as_float(hp0 & 0xffff0000u);
                float h2 = __uint_as_float(hp1 << 16), h3 = __uint_as_float(hp1 & 0xffff0000u);
                CVT_BF16X2(lp0, f0 - h0, f1 - h1);
                CVT_BF16X2(lp1, f2 - h2, f3 - h3);
                int i0 = (tid & 1) * 8 + c4 * 4 + half * 2;
                #pragma unroll
                for (int u = 0; u < 2; u++) {
                    int i = i0 + u;
                    uint32_t hv = u ? hp1 : hp0;
                    uint32_t lv = u ? lp1 : lp0;
                    int chih = (i >> 2);
                    int chil = 4 + (i >> 2);
                    *(uint32_t*)(smem + SM_Q + m * 128 + ((chih ^ sw) << 4) + (i & 3) * 4) = hv;
                    *(uint32_t*)(smem + SM_Q + m * 128 + ((chil ^ sw) << 4) + (i & 3) * 4) = lv;
                }
            }
        }
    }
    __syncthreads();

    // ---- Q A-fragments ----
    uint32_t qfh[2][4], qfl[2][4];
    {
        const int m_off = (lane & 7) + ((lane >> 3) & 1) * 8;
        const int coff  = (lane >> 4) & 1;
        const int m = wid * 16 + m_off;
        const uint32_t qrow = sb + SM_Q + m * 128;
        #pragma unroll
        for (int k16 = 0; k16 < 2; k16++) {
            int ch = 2 * k16 + coff;
            ldm_x4(qfh[k16], qrow + (((ch)     ^ (m & 7)) << 4));
            ldm_x4(qfl[k16], qrow + (((ch + 4) ^ (m & 7)) << 4));
        }
    }

    const int kb_row = (lane & 7) + ((lane >> 4) & 1) * 8;
    const int kb_c   = (lane >> 3) & 1;

    const unsigned* mb0 = mbits + (size_t)(b * S_LEN + q0 + wid * 16 + (lane >> 2)) * MWORDS;
    const unsigned* mb1 = mb0 + 8 * MWORDS;

    float l0 = 0.f, l1 = 0.f;
    float o[4][4];
    #pragma unroll
    for (int i = 0; i < 4; i++)
        #pragma unroll
        for (int j = 0; j < 4; j++) o[i][j] = 0.f;

    for (int t = 0; t < 32; t++) {
        if (t < 31) {
            uint32_t d1 = sb + SM_KV + ((t + 1) & 1) * 16384;
            const char* ks = ksrc + (size_t)(t + 1) * 8192;
            const char* vs = vsrc + (size_t)(t + 1) * 8192;
            CP16(d1 + tid * 16,                ks + tid * 16);
            CP16(d1 + (tid + 256) * 16,        ks + (tid + 256) * 16);
            CP16(d1 + 8192 + tid * 16,         vs + tid * 16);
            CP16(d1 + 8192 + (tid + 256) * 16, vs + (tid + 256) * 16);
            CP_COMMIT();
            CP_WAIT1();
        } else {
            CP_WAIT0();
        }
        __syncthreads();

        const uint32_t kbase = sb + SM_KV + (t & 1) * 16384;
        const uint32_t vbase = kbase + 8192;

        // ---- QK^T ----
        float c[8][4];
        #pragma unroll
        for (int i = 0; i < 8; i++)
            #pragma unroll
            for (int j = 0; j < 4; j++) c[i][j] = 0.f;

        #pragma unroll
        for (int k16 = 0; k16 < 2; k16++) {
            #pragma unroll
            for (int np = 0; np < 4; np++) {
                const int key = np * 16 + kb_row;
                const int ch  = 2 * k16 + kb_c;
                uint32_t bhf[4], blf[4];
                ldm_x4(bhf, kbase + key * 128 + (((ch ^ (key & 7))) << 4));
                mma_bf16(c[2 * np],     qfh[k16], bhf + 0);
                mma_bf16(c[2 * np + 1], qfh[k16], bhf + 2);
                mma_bf16(c[2 * np],     qfl[k16], bhf + 0);
                mma_bf16(c[2 * np + 1], qfl[k16], bhf + 2);
                ldm_x4(blf, kbase + key * 128 + ((((ch + 4) ^ (key & 7))) << 4));
                mma_bf16(c[2 * np],     qfh[k16], blf + 0);
                mma_bf16(c[2 * np + 1], qfh[k16], blf + 2);
            }
        }

        // ---- softmax -> P hi/lo fragments ----
        const uint64_t mw0 = *(const uint64_t*)(mb0 + t * 2);
        const uint64_t mw1 = *(const uint64_t*)(mb1 + t * 2);
        uint32_t aph[4][4], apl[4][4];
        #pragma unroll
        for (int jj = 0; jj < 4; jj++) {
            #pragma unroll
            for (int half = 0; half < 2; half++) {
                const int j = 2 * jj + half;
                const int colb = j * 8 + (lane & 3) * 2;
                float p0 = ((mw0 >> colb)       & 1) ? ex2(c[j][0]) : 0.f;
                float p1 = ((mw0 >> (colb + 1)) & 1) ? ex2(c[j][1]) : 0.f;
                float p2 = ((mw1 >> colb)       & 1) ? ex2(c[j][2]) : 0.f;
                float p3 = ((mw1 >> (colb + 1)) & 1) ? ex2(c[j][3]) : 0.f;
                l0 += p0 + p1; l1 += p2 + p3;
                uint32_t hp01, hp23;
                CVT_BF16X2(hp01, p0, p1);
                CVT_BF16X2(hp23, p2, p3);
                float r0 = p0 - __uint_as_float(hp01 << 16);
                float r1 = p1 - __uint_as_float(hp01 & 0xffff0000u);
                float r2 = p2 - __uint_as_float(hp23 << 16);
                float r3 = p3 - __uint_as_float(hp23 & 0xffff0000u);
                uint32_t lp01, lp23;
                CVT_BF16X2(lp01, r0, r1);
                CVT_BF16X2(lp23, r2, r3);
                aph[jj][half * 2]     = hp01;
                aph[jj][half * 2 + 1] = hp23;
                apl[jj][half * 2]     = lp01;
                apl[jj][half * 2 + 1] = lp23;
            }
        }

        // ---- PV: O += ph*vh + pl*vh + ph*vl (vl at SAME chunk, separate image) ----
        #pragma unroll
        for (int k16 = 0; k16 < 4; k16++) {
            #pragma unroll
            for (int np = 0; np < 2; np++) {
                const int d  = np * 16 + kb_row;
                const int ch = 2 * k16 + kb_c;
                const uint32_t swo = (((ch ^ (d & 7))) << 4);
                uint32_t bvh[4], bvl[4];
                ldm_x4(bvh, vbase + d * 128 + swo);
                mma_bf16(o[2 * np],     aph[k16], bvh + 0);
                mma_bf16(o[2 * np + 1], aph[k16], bvh + 2);
                mma_bf16(o[2 * np],     apl[k16], bvh + 0);
                mma_bf16(o[2 * np + 1], apl[k16], bvh + 2);
                ldm_x4(bvl, vbase + 4096 + d * 128 + swo);   // THE FIX (R4 semantics)
                mma_bf16(o[2 * np],     aph[k16], bvl + 0);
                mma_bf16(o[2 * np + 1], aph[k16], bvl + 2);
            }
        }
        __syncthreads();
    }

    // ---- finalize: normalize and write packed bf16 hi/lo GEMM-A format ----
    l0 += __shfl_xor_sync(0xffffffffu, l0, 1);
    l0 += __shfl_xor_sync(0xffffffffu, l0, 2);
    l1 += __shfl_xor_sync(0xffffffffu, l1, 1);
    l1 += __shfl_xor_sync(0xffffffffu, l1, 2);
    const float inv0 = 1.f / l0, inv1 = 1.f / l1;

    const int r0g = q0 + wid * 16 + (lane >> 2);
    const int r1g = r0g + 8;
    uint32_t* Op32 = (uint32_t*)g_Op;
    const size_t base0 = ((size_t)h * M_ROWS + b * S_LEN + r0g) * 32;
    const size_t base1 = ((size_t)h * M_ROWS + b * S_LEN + r1g) * 32;
    const int sw0 = (r0g & 7) << 3;
    const int sw1 = (r1g & 7) << 3;
    #pragma unroll
    for (int j = 0; j < 4; j++) {
        const int d = j * 8 + (lane & 3) * 2;
        float v0 = o[j][0] * inv0, v1 = o[j][1] * inv0;
        float v2 = o[j][2] * inv1, v3 = o[j][3] * inv1;
        uint32_t h01, h23;
        CVT_BF16X2(h01, v0, v1);
        CVT_BF16X2(h23, v2, v3);
        float r0l = v0 - __uint_as_float(h01 << 16);
        float r1l = v1 - __uint_as_float(h01 & 0xffff0000u);
        float r2l = v2 - __uint_as_float(h23 << 16);
        float r3l = v3 - __uint_as_float(h23 & 0xffff0000u);
        uint32_t l01, l23;
        CVT_BF16X2(l01, r0l, r1l);
        CVT_BF16X2(l23, r2l, r3l);
        Op32[base0 + (((d)      ^ sw0) >> 1)] = h01;
        Op32[base0 + (((32 + d) ^ sw0) >> 1)] = l01;
        Op32[base1 + (((d)      ^ sw1) >> 1)] = h23;
        Op32[base1 + (((32 + d) ^ sw1) >> 1)] = l23;
    }
}

// ---------------------------------------------------------------------------
// Launch
// ---------------------------------------------------------------------------
extern "C" void kernel_launch(void* const* d_in, const int* in_sizes, int n_in,
                              void* d_out, int out_size)
{
    const float* query = (const float*)d_in[0];
    const float* key   = (const float*)d_in[1];
    const float* value = (const float*)d_in[2];
    const int*   mask  = (const int*)  d_in[3];
    const float* Wq = (const float*)d_in[4];
    const float* bq = (const float*)d_in[5];
    const float* Wk = (const float*)d_in[6];
    const float* bk = (const float*)d_in[7];
    const float* Wv = (const float*)d_in[8];
    const float* bv = (const float*)d_in[9];
    const float* Wo = (const float*)d_in[10];
    const float* bo = (const float*)d_in[11];
    float* out = (float*)d_out;

    float *Qb, *Kb, *Vb;
    unsigned* MBp;
    __nv_bfloat16 *Kpp, *Vpp, *Aq, *Ak, *Av, *Op, *Wp;
    cudaGetSymbolAddress((void**)&Qb, g_Q);
    cudaGetSymbolAddress((void**)&Kb, g_K);
    cudaGetSymbolAddress((void**)&Vb, g_V);
    cudaGetSymbolAddress((void**)&MBp, g_MB);
    cudaGetSymbolAddress((void**)&Kpp, g_Kp);
    cudaGetSymbolAddress((void**)&Vpp, g_Vp);
    cudaGetSymbolAddress((void**)&Aq, g_Aq);
    cudaGetSymbolAddress((void**)&Ak, g_Ak);
    cudaGetSymbolAddress((void**)&Av, g_Av);
    cudaGetSymbolAddress((void**)&Op, g_Op);
    cudaGetSymbolAddress((void**)&Wp, g_Wp);

    cudaFuncSetAttribute(attn_mma_kernel, cudaFuncAttributeMaxDynamicSharedMemorySize, ATTN_SMEM);
    cudaFuncSetAttribute(gemm_tc_qkv, cudaFuncAttributeMaxDynamicSharedMemorySize, GEMM_SMEM);
    cudaFuncSetAttribute(gemm_tc_one, cudaFuncAttributeMaxDynamicSharedMemorySize, GEMM_SMEM);

    pack_mask_kernel<<<(BATCH * S_LEN * S_LEN) / 256, 256>>>(mask, MBp);
    pack_w_kernel<<<(4 * 8 * 256 * 64) / 256, 256>>>(Wq, Wk, Wv, Wo, Wp);
    pack_a3_kernel<<<dim3((8 * M_ROWS * 64) / 256, 3), 256>>>(query, key, value, Aq, Ak, Av);

    gemm_tc_qkv<<<dim3(4, 64, 3), 256, GEMM_SMEM>>>(Aq, Ak, Av, Wp,
                                                    bq, bk, bv, Qb, Kb, Vb);

    pack_k_kernel<<<(NBH * S_LEN * 64) / 256, 256>>>(Kb, Kpp);
    pack_v_kernel<<<(NBH * 32 * 4096) / 256, 256>>>(Vb, Vpp);

    dim3 attn_grid(S_LEN / 128, NHEADS, BATCH);   // (16, 8, 4)
    attn_mma_kernel<<<attn_grid, 256, ATTN_SMEM>>>(Qb, Kpp, Vpp, MBp);

    gemm_tc_one<<<dim3(4, 64), 256, GEMM_SMEM>>>(Op, Wp + (size_t)3 * 131072, bo, out);
}

// round 11
// speedup vs baseline: 3.4198x; 1.3243x over previous
#include <cuda_runtime.h>
#include <cuda_bf16.h>
#include <cuda_fp16.h>
#include <cstdint>
#include <math.h>

// Problem constants
#define BATCH   4
#define S_LEN   2048
#define DMODEL  256
#define NHEADS  8
#define HD      32
#define M_ROWS  (BATCH * S_LEN)   // 8192
#define MWORDS  (S_LEN / 32)      // 64 mask words per row
#define NBH     (BATCH * NHEADS)  // 32

// Scratch (device globals: allocation-free per harness rules)
__device__ float          g_Q[M_ROWS * DMODEL];
__device__ float          g_K[M_ROWS * DMODEL];
__device__ float          g_V[M_ROWS * DMODEL];
__device__ unsigned       g_MB[BATCH * S_LEN * MWORDS];        // packed mask bits
__device__ __half         g_Kp16[(size_t)NBH * S_LEN * 32];    // attn K fp16, swizzled 64B rows
__device__ __half         g_Vp16[(size_t)NBH * 32 * 2048];     // attn V^T fp16, 4KB/tile swizzled
// GEMM operand packs: A-format [blk 0..7][row][64 bf16], SW128 swizzled per row
__device__ __nv_bfloat16  g_Aq[(size_t)8 * M_ROWS * 64];
__device__ __nv_bfloat16  g_Ak[(size_t)8 * M_ROWS * 64];
__device__ __nv_bfloat16  g_Av[(size_t)8 * M_ROWS * 64];
__device__ __nv_bfloat16  g_Op[(size_t)8 * M_ROWS * 64];       // attn output, packed directly
__device__ __nv_bfloat16  g_Wp[(size_t)4 * 8 * 256 * 64];      // weights q,k,v,o

// ---------------------------------------------------------------------------
// Helpers
// ---------------------------------------------------------------------------
__device__ __forceinline__ uint32_t smem_u32(const void* p) {
    uint32_t a;
    asm("{ .reg .u64 t; cvta.to.shared.u64 t, %1; cvt.u32.u64 %0, t; }" : "=r"(a) : "l"(p));
    return a;
}
__device__ __forceinline__ float ex2(float x) {
    float y; asm("ex2.approx.f32 %0, %1;" : "=f"(y) : "f"(x)); return y;
}
// pack two fp32 -> bf16x2 (lo = p0, hi = p1)
#define CVT_BF16X2(result, p0, p1) \
    asm("cvt.rn.satfinite.bf16x2.f32 %0, %1, %2;" : "=r"(result) : "f"(p1), "f"(p0))
// pack two fp32 -> f16x2 (lo = p0, hi = p1)
#define CVT_F16X2(result, p0, p1) \
    asm("cvt.rn.f16x2.f32 %0, %1, %2;" : "=r"(result) : "f"(p1), "f"(p0))

__device__ __forceinline__ void ldm_x4(uint32_t (&r)[4], uint32_t addr) {
    asm volatile("ldmatrix.sync.aligned.m8n8.x4.shared.b16 {%0,%1,%2,%3}, [%4];"
                 : "=r"(r[0]), "=r"(r[1]), "=r"(r[2]), "=r"(r[3]) : "r"(addr));
}
__device__ __forceinline__ void mma_bf16(float (&d)[4], const uint32_t* a, const uint32_t* b) {
    asm volatile("mma.sync.aligned.m16n8k16.row.col.f32.bf16.bf16.f32 "
                 "{%0,%1,%2,%3}, {%4,%5,%6,%7}, {%8,%9}, {%0,%1,%2,%3};"
                 : "+f"(d[0]), "+f"(d[1]), "+f"(d[2]), "+f"(d[3])
                 : "r"(a[0]), "r"(a[1]), "r"(a[2]), "r"(a[3]), "r"(b[0]), "r"(b[1]));
}
__device__ __forceinline__ void mma_f16(float (&d)[4], const uint32_t* a, const uint32_t* b) {
    asm volatile("mma.sync.aligned.m16n8k16.row.col.f32.f16.f16.f32 "
                 "{%0,%1,%2,%3}, {%4,%5,%6,%7}, {%8,%9}, {%0,%1,%2,%3};"
                 : "+f"(d[0]), "+f"(d[1]), "+f"(d[2]), "+f"(d[3])
                 : "r"(a[0]), "r"(a[1]), "r"(a[2]), "r"(a[3]), "r"(b[0]), "r"(b[1]));
}

#define CP16(dst, src) \
    asm volatile("cp.async.cg.shared.global [%0], [%1], 16;" :: "r"(dst), "l"(src))
#define CP_COMMIT() asm volatile("cp.async.commit_group;" ::: "memory")
#define CP_WAIT1()  asm volatile("cp.async.wait_group 1;" ::: "memory")
#define CP_WAIT0()  asm volatile("cp.async.wait_group 0;" ::: "memory")

// ---------------------------------------------------------------------------
// Mask bit-pack
// ---------------------------------------------------------------------------
__global__ __launch_bounds__(256) void pack_mask_kernel(
    const int* __restrict__ mask, unsigned* __restrict__ bits)
{
    int idx = blockIdx.x * 256 + threadIdx.x;
    unsigned w = __ballot_sync(0xffffffffu, mask[idx] != 0);
    if ((threadIdx.x & 31) == 0) bits[idx >> 5] = w;
}

// ---------------------------------------------------------------------------
// Pack activations (q/k/v inputs) into GEMM A-format: [blk][m][64], swizzled
// ---------------------------------------------------------------------------
__global__ __launch_bounds__(256) void pack_a3_kernel(
    const float* __restrict__ q, const float* __restrict__ k, const float* __restrict__ v,
    __nv_bfloat16* __restrict__ Aq, __nv_bfloat16* __restrict__ Ak, __nv_bfloat16* __restrict__ Av)
{
    const float* src; __nv_bfloat16* dst;
    if (blockIdx.y == 0)      { src = q; dst = Aq; }
    else if (blockIdx.y == 1) { src = k; dst = Ak; }
    else                      { src = v; dst = Av; }
    int idx = blockIdx.x * 256 + threadIdx.x;     // 8 * 8192 * 64
    int c   = idx & 63;
    int m   = (idx >> 6) & (M_ROWS - 1);
    int blk = idx >> 19;
    int d = blk * 32 + (c & 31);
    float val = src[(size_t)m * DMODEL + d];
    __nv_bfloat16 hi = __float2bfloat16(val);
    __nv_bfloat16 out = (c < 32) ? hi : __float2bfloat16(val - __bfloat162float(hi));
    dst[(((size_t)blk * M_ROWS + m) << 6) + (c ^ ((m & 7) << 3))] = out;
}

// ---------------------------------------------------------------------------
// Pack all 4 weight matrices: [w][blk][n][64], swizzled
// ---------------------------------------------------------------------------
__global__ __launch_bounds__(256) void pack_w_kernel(
    const float* __restrict__ Wq, const float* __restrict__ Wk,
    const float* __restrict__ Wv, const float* __restrict__ Wo,
    __nv_bfloat16* __restrict__ Wp)
{
    int idx = blockIdx.x * 256 + threadIdx.x;     // 4 * 8 * 256 * 64
    int c   = idx & 63;
    int n   = (idx >> 6) & 255;
    int blk = (idx >> 14) & 7;
    int w   = idx >> 17;
    const float* W = (w == 0) ? Wq : (w == 1) ? Wk : (w == 2) ? Wv : Wo;
    int d = blk * 32 + (c & 31);
    float val = W[(size_t)n * DMODEL + d];
    __nv_bfloat16 hi = __float2bfloat16(val);
    __nv_bfloat16 out = (c < 32) ? hi : __float2bfloat16(val - __bfloat162float(hi));
    Wp[(((size_t)(w * 8 + blk) * 256 + n) << 6) + (c ^ ((n & 7) << 3))] = out;
}

// ---------------------------------------------------------------------------
// K pack (fp16 single image): per (b,h,s): 32 fp16 = 64B row,
// swizzle chunk (c>>3) ^ ((s>>1)&3)  -> conflict-free ldmatrix on 64B rows
// ---------------------------------------------------------------------------
__global__ __launch_bounds__(256) void pack_k16_kernel(
    const float* __restrict__ K, __half* __restrict__ Kp)
{
    int idx = blockIdx.x * 256 + threadIdx.x;      // NBH*2048*32
    int c = idx & 31;
    int row = idx >> 5;
    int s = row & (S_LEN - 1);
    int bh = row >> 11;
    int b = bh >> 3, h = bh & 7;
    float v = K[(size_t)(b * S_LEN + s) * DMODEL + h * HD + c];
    Kp[(size_t)row * 32 + (c ^ (((s >> 1) & 3) << 3))] = __float2half_rn(v);
}

// ---------------------------------------------------------------------------
// V pack (fp16 single image): per (b,h,ktile): V^T 32d x 64key, 128B rows,
// swizzle (key) ^ ((d&7)<<3)
// ---------------------------------------------------------------------------
__global__ __launch_bounds__(256) void pack_v16_kernel(
    const float* __restrict__ V, __half* __restrict__ Vp)
{
    int idx = blockIdx.x * 256 + threadIdx.x;      // NBH*32*32*64
    int key = idx & 63;
    int d   = (idx >> 6) & 31;
    int t   = (idx >> 11) & 31;
    int bh  = idx >> 16;
    int b = bh >> 3, h = bh & 7;
    float v = V[(size_t)(b * S_LEN + t * 64 + key) * DMODEL + h * HD + d];
    Vp[(size_t)bh * 65536 + t * 2048 + d * 64 + (key ^ ((d & 7) << 3))] = __float2half_rn(v);
}

// ---------------------------------------------------------------------------
// Tensor-core GEMM: C[M,256] = A[M,256] @ W^T + bias, bf16 hi/lo 3-term.
// ---------------------------------------------------------------------------
#define GEMM_SMEM 98304

__device__ __forceinline__ void gemm_tc_body(
    const __nv_bfloat16* __restrict__ Ap, const __nv_bfloat16* __restrict__ Wp,
    const float* __restrict__ bias, float* __restrict__ C, char* smem)
{
    const uint32_t sb = smem_u32(smem);
    const int tid = threadIdx.x, lane = tid & 31, wid = tid >> 5;
    const int n0 = blockIdx.x * 64, m0 = blockIdx.y * 128;
    const char* Ab = (const char*)Ap;
    const char* Wb = (const char*)Wp;

    auto stage = [&](int t, uint32_t buf) {
        #pragma unroll
        for (int i = 0; i < 8; i++) {
            int g = i * 256 + tid;
            int blk = g >> 10, row = (g >> 3) & 127, ch = g & 7;
            CP16(sb + buf + blk * 16384 + row * 128 + ch * 16,
                 Ab + ((size_t)(t * 2 + blk) * M_ROWS + m0 + row) * 128 + ch * 16);
        }
        #pragma unroll
        for (int i = 0; i < 4; i++) {
            int g = i * 256 + tid;
            int blk = g >> 9, row = (g >> 3) & 63, ch = g & 7;
            CP16(sb + buf + 32768 + blk * 8192 + row * 128 + ch * 16,
                 Wb + ((size_t)(t * 2 + blk) * 256 + n0 + row) * 128 + ch * 16);
        }
        CP_COMMIT();
    };

    stage(0, 0);

    float c[8][4];
    #pragma unroll
    for (int i = 0; i < 8; i++)
        #pragma unroll
        for (int j = 0; j < 4; j++) c[i][j] = 0.f;

    const int m_off = (lane & 7) + ((lane >> 3) & 1) * 8;
    const int coff  = (lane >> 4) & 1;
    const int m = wid * 16 + m_off;
    const int kb_row = (lane & 7) + ((lane >> 4) & 1) * 8;
    const int kb_c   = (lane >> 3) & 1;

    for (int t = 0; t < 4; t++) {
        if (t < 3) { stage(t + 1, ((t + 1) & 1) * 49152); CP_WAIT1(); }
        else       { CP_WAIT0(); }
        __syncthreads();

        const uint32_t abase = sb + (t & 1) * 49152;
        const uint32_t wbase = abase + 32768;

        #pragma unroll
        for (int k16 = 0; k16 < 4; k16++) {
            const int ablk = k16 >> 1;
            const int ch = 2 * (k16 & 1) + coff;
            const uint32_t arow = abase + ablk * 16384 + m * 128;
            uint32_t afh[4], afl[4];
            ldm_x4(afh, arow + (((ch)     ^ (m & 7)) << 4));
            ldm_x4(afl, arow + (((ch + 4) ^ (m & 7)) << 4));
            #pragma unroll
            for (int np = 0; np < 4; np++) {
                const int n = np * 16 + kb_row;
                const uint32_t wrow = wbase + ablk * 8192 + n * 128;
                const int wch = 2 * (k16 & 1) + kb_c;
                uint32_t bhf[4], blf[4];
                ldm_x4(bhf, wrow + (((wch)     ^ (n & 7)) << 4));
                mma_bf16(c[2 * np],     afh, bhf + 0);
                mma_bf16(c[2 * np + 1], afh, bhf + 2);
                mma_bf16(c[2 * np],     afl, bhf + 0);
                mma_bf16(c[2 * np + 1], afl, bhf + 2);
                ldm_x4(blf, wrow + (((wch + 4) ^ (n & 7)) << 4));
                mma_bf16(c[2 * np],     afh, blf + 0);
                mma_bf16(c[2 * np + 1], afh, blf + 2);
            }
        }
        __syncthreads();
    }

    const int r0 = m0 + wid * 16 + (lane >> 2);
    #pragma unroll
    for (int np = 0; np < 4; np++) {
        #pragma unroll
        for (int half = 0; half < 2; half++) {
            const int col = n0 + np * 16 + half * 8 + (lane & 3) * 2;
            const float b0 = bias[col], b1 = bias[col + 1];
            float* p0 = C + (size_t)r0 * DMODEL + col;
            *(float2*)p0 = make_float2(c[2 * np + half][0] + b0, c[2 * np + half][1] + b1);
            *(float2*)(p0 + 8 * DMODEL) = make_float2(c[2 * np + half][2] + b0, c[2 * np + half][3] + b1);
        }
    }
}

__global__ __launch_bounds__(256, 2) void gemm_tc_qkv(
    const __nv_bfloat16* __restrict__ Aq, const __nv_bfloat16* __restrict__ Ak,
    const __nv_bfloat16* __restrict__ Av, const __nv_bfloat16* __restrict__ Wp,
    const float* __restrict__ bq, const float* __restrict__ bk, const float* __restrict__ bv,
    float* __restrict__ Qo, float* __restrict__ Ko, float* __restrict__ Vo)
{
    extern __shared__ char smem[];
    const __nv_bfloat16* A; const __nv_bfloat16* W; const float* b; float* C;
    if (blockIdx.z == 0)      { A = Aq; W = Wp;                       b = bq; C = Qo; }
    else if (blockIdx.z == 1) { A = Ak; W = Wp + (size_t)1 * 131072;  b = bk; C = Ko; }
    else                      { A = Av; W = Wp + (size_t)2 * 131072;  b = bv; C = Vo; }
    gemm_tc_body(A, W, b, C, smem);
}

__global__ __launch_bounds__(256, 2) void gemm_tc_one(
    const __nv_bfloat16* __restrict__ Ap, const __nv_bfloat16* __restrict__ Wp,
    const float* __restrict__ bias, float* __restrict__ C)
{
    extern __shared__ char smem[];
    gemm_tc_body(Ap, Wp, bias, C, smem);
}

// ---------------------------------------------------------------------------
// fp16 single-pass mma flash attention.
// Per key tile per warp: 8 ldm + 16 mma (QK) + 8 ldm + 16 mma (PV).
// smem: KV double buffer [2][8KB] at 0; Q fp16 (128 x 64B) at 16KB.
// Epilogue writes packed bf16 hi/lo GEMM-A format into g_Op (exact path).
// ---------------------------------------------------------------------------
#define SM_KV 0
#define SM_Q  16384
#define ATTN_SMEM 24576

__global__ __launch_bounds__(256, 2) void attn_mma_kernel(
    const float* __restrict__ Q, const __half* __restrict__ Kp,
    const __half* __restrict__ Vp, const unsigned* __restrict__ mbits)
{
    extern __shared__ char smem[];
    const uint32_t sb = smem_u32(smem);
    const int tid = threadIdx.x;
    const int lane = tid & 31, wid = tid >> 5;
    const int b = blockIdx.z, h = blockIdx.y;
    const int q0 = blockIdx.x * 128;
    const int bh = b * NHEADS + h;
    const float SC = 0.17677669529663687f * 1.4426950408889634f; // 1/sqrt(32)*log2e

    const char* ksrc = (const char*)(Kp + (size_t)bh * 65536);
    const char* vsrc = (const char*)(Vp + (size_t)bh * 65536);

    // ---- prefetch tile 0 (K 4KB + V 4KB) ----
    {
        uint32_t d0 = sb + SM_KV;
        CP16(d0 + tid * 16,        ksrc + tid * 16);
        CP16(d0 + 4096 + tid * 16, vsrc + tid * 16);
        CP_COMMIT();
    }

    // ---- Q staging: fp16 single image, 64B rows, chunk swizzle (m>>1)&3 ----
    {
        const int m = tid >> 1;
        const float* qp = Q + ((size_t)(b * S_LEN + q0 + m)) * DMODEL + h * HD + (tid & 1) * 16;
        const int swq = (m >> 1) & 3;
        #pragma unroll
        for (int c4 = 0; c4 < 4; c4++) {
            float4 v4 = *(const float4*)&qp[c4 * 4];
            uint32_t p0, p1;
            CVT_F16X2(p0, v4.x * SC, v4.y * SC);
            CVT_F16X2(p1, v4.z * SC, v4.w * SC);
            const int c0 = (tid & 1) * 16 + c4 * 4;
            char* dst = smem + SM_Q + m * 64 + (((c0 >> 3) ^ swq) << 4) + (c0 & 7) * 2;
            *(uint32_t*)dst = p0;
            *(uint32_t*)(dst + 4) = p1;
        }
    }
    __syncthreads();

    // ---- Q A-fragments (fp16, single image) ----
    uint32_t qf[2][4];
    {
        const int m_off = (lane & 7) + ((lane >> 3) & 1) * 8;
        const int coff  = (lane >> 4) & 1;
        const int m = wid * 16 + m_off;
        const uint32_t qrow = sb + SM_Q + m * 64;
        const int swq = (m >> 1) & 3;
        #pragma unroll
        for (int k16 = 0; k16 < 2; k16++) {
            int ch = 2 * k16 + coff;
            ldm_x4(qf[k16], qrow + ((ch ^ swq) << 4));
        }
    }

    const int kb_row = (lane & 7) + ((lane >> 4) & 1) * 8;
    const int kb_c   = (lane >> 3) & 1;

    const unsigned* mb0 = mbits + (size_t)(b * S_LEN + q0 + wid * 16 + (lane >> 2)) * MWORDS;
    const unsigned* mb1 = mb0 + 8 * MWORDS;

    float l0 = 0.f, l1 = 0.f;
    float o[4][4];
    #pragma unroll
    for (int i = 0; i < 4; i++)
        #pragma unroll
        for (int j = 0; j < 4; j++) o[i][j] = 0.f;

    for (int t = 0; t < 32; t++) {
        if (t < 31) {
            uint32_t d1 = sb + SM_KV + ((t + 1) & 1) * 8192;
            const char* ks = ksrc + (size_t)(t + 1) * 4096;
            const char* vs = vsrc + (size_t)(t + 1) * 4096;
            CP16(d1 + tid * 16,        ks + tid * 16);
            CP16(d1 + 4096 + tid * 16, vs + tid * 16);
            CP_COMMIT();
            CP_WAIT1();
        } else {
            CP_WAIT0();
        }
        __syncthreads();

        const uint32_t kbase = sb + SM_KV + (t & 1) * 8192;
        const uint32_t vbase = kbase + 4096;

        // ---- QK^T (fp16 single pass): 8 ldm + 16 mma ----
        float c[8][4];
        #pragma unroll
        for (int i = 0; i < 8; i++)
            #pragma unroll
            for (int j = 0; j < 4; j++) c[i][j] = 0.f;

        #pragma unroll
        for (int k16 = 0; k16 < 2; k16++) {
            #pragma unroll
            for (int np = 0; np < 4; np++) {
                const int key = np * 16 + kb_row;
                const int ch  = 2 * k16 + kb_c;
                uint32_t bf[4];
                ldm_x4(bf, kbase + key * 64 + ((ch ^ ((key >> 1) & 3)) << 4));
                mma_f16(c[2 * np],     qf[k16], bf + 0);
                mma_f16(c[2 * np + 1], qf[k16], bf + 2);
            }
        }

        // ---- softmax -> P fp16 fragments ----
        const uint64_t mw0 = *(const uint64_t*)(mb0 + t * 2);
        const uint64_t mw1 = *(const uint64_t*)(mb1 + t * 2);
        uint32_t ap[4][4];
        #pragma unroll
        for (int jj = 0; jj < 4; jj++) {
            #pragma unroll
            for (int half = 0; half < 2; half++) {
                const int j = 2 * jj + half;
                const int colb = j * 8 + (lane & 3) * 2;
                float p0 = ((mw0 >> colb)       & 1) ? ex2(c[j][0]) : 0.f;
                float p1 = ((mw0 >> (colb + 1)) & 1) ? ex2(c[j][1]) : 0.f;
                float p2 = ((mw1 >> colb)       & 1) ? ex2(c[j][2]) : 0.f;
                float p3 = ((mw1 >> (colb + 1)) & 1) ? ex2(c[j][3]) : 0.f;
                l0 += p0 + p1; l1 += p2 + p3;
                CVT_F16X2(ap[jj][half * 2],     p0, p1);
                CVT_F16X2(ap[jj][half * 2 + 1], p2, p3);
            }
        }

        // ---- PV (fp16 single pass): 8 ldm + 16 mma ----
        #pragma unroll
        for (int k16 = 0; k16 < 4; k16++) {
            #pragma unroll
            for (int np = 0; np < 2; np++) {
                const int d  = np * 16 + kb_row;
                const int ch = 2 * k16 + kb_c;
                uint32_t bv[4];
                ldm_x4(bv, vbase + d * 128 + ((ch ^ (d & 7)) << 4));
                mma_f16(o[2 * np],     ap[k16], bv + 0);
                mma_f16(o[2 * np + 1], ap[k16], bv + 2);
            }
        }
        __syncthreads();
    }

    // ---- finalize: normalize and write packed bf16 hi/lo GEMM-A format ----
    l0 += __shfl_xor_sync(0xffffffffu, l0, 1);
    l0 += __shfl_xor_sync(0xffffffffu, l0, 2);
    l1 += __shfl_xor_sync(0xffffffffu, l1, 1);
    l1 += __shfl_xor_sync(0xffffffffu, l1, 2);
    const float inv0 = 1.f / l0, inv1 = 1.f / l1;

    const int r0g = q0 + wid * 16 + (lane >> 2);
    const int r1g = r0g + 8;
    uint32_t* Op32 = (uint32_t*)g_Op;
    const size_t base0 = ((size_t)h * M_ROWS + b * S_LEN + r0g) * 32;
    const size_t base1 = ((size_t)h * M_ROWS + b * S_LEN + r1g) * 32;
    const int sw0 = (r0g & 7) << 3;
    const int sw1 = (r1g & 7) << 3;
    #pragma unroll
    for (int j = 0; j < 4; j++) {
        const int d = j * 8 + (lane & 3) * 2;
        float v0 = o[j][0] * inv0, v1 = o[j][1] * inv0;
        float v2 = o[j][2] * inv1, v3 = o[j][3] * inv1;
        uint32_t h01, h23;
        CVT_BF16X2(h01, v0, v1);
        CVT_BF16X2(h23, v2, v3);
        float r0l = v0 - __uint_as_float(h01 << 16);
        float r1l = v1 - __uint_as_float(h01 & 0xffff0000u);
        float r2l = v2 - __uint_as_float(h23 << 16);
        float r3l = v3 - __uint_as_float(h23 & 0xffff0000u);
        uint32_t l01, l23;
        CVT_BF16X2(l01, r0l, r1l);
        CVT_BF16X2(l23, r2l, r3l);
        Op32[base0 + (((d)      ^ sw0) >> 1)] = h01;
        Op32[base0 + (((32 + d) ^ sw0) >> 1)] = l01;
        Op32[base1 + (((d)      ^ sw1) >> 1)] = h23;
        Op32[base1 + (((32 + d) ^ sw1) >> 1)] = l23;
    }
}

// ---------------------------------------------------------------------------
// Launch
// ---------------------------------------------------------------------------
extern "C" void kernel_launch(void* const* d_in, const int* in_sizes, int n_in,
                              void* d_out, int out_size)
{
    const float* query = (const float*)d_in[0];
    const float* key   = (const float*)d_in[1];
    const float* value = (const float*)d_in[2];
    const int*   mask  = (const int*)  d_in[3];
    const float* Wq = (const float*)d_in[4];
    const float* bq = (const float*)d_in[5];
    const float* Wk = (const float*)d_in[6];
    const float* bk = (const float*)d_in[7];
    const float* Wv = (const float*)d_in[8];
    const float* bv = (const float*)d_in[9];
    const float* Wo = (const float*)d_in[10];
    const float* bo = (const float*)d_in[11];
    float* out = (float*)d_out;

    float *Qb, *Kb, *Vb;
    unsigned* MBp;
    __half *Kpp, *Vpp;
    __nv_bfloat16 *Aq, *Ak, *Av, *Op, *Wp;
    cudaGetSymbolAddress((void**)&Qb, g_Q);
    cudaGetSymbolAddress((void**)&Kb, g_K);
    cudaGetSymbolAddress((void**)&Vb, g_V);
    cudaGetSymbolAddress((void**)&MBp, g_MB);
    cudaGetSymbolAddress((void**)&Kpp, g_Kp16);
    cudaGetSymbolAddress((void**)&Vpp, g_Vp16);
    cudaGetSymbolAddress((void**)&Aq, g_Aq);
    cudaGetSymbolAddress((void**)&Ak, g_Ak);
    cudaGetSymbolAddress((void**)&Av, g_Av);
    cudaGetSymbolAddress((void**)&Op, g_Op);
    cudaGetSymbolAddress((void**)&Wp, g_Wp);

    cudaFuncSetAttribute(attn_mma_kernel, cudaFuncAttributeMaxDynamicSharedMemorySize, ATTN_SMEM);
    cudaFuncSetAttribute(gemm_tc_qkv, cudaFuncAttributeMaxDynamicSharedMemorySize, GEMM_SMEM);
    cudaFuncSetAttribute(gemm_tc_one, cudaFuncAttributeMaxDynamicSharedMemorySize, GEMM_SMEM);

    pack_mask_kernel<<<(BATCH * S_LEN * S_LEN) / 256, 256>>>(mask, MBp);
    pack_w_kernel<<<(4 * 8 * 256 * 64) / 256, 256>>>(Wq, Wk, Wv, Wo, Wp);
    pack_a3_kernel<<<dim3((8 * M_ROWS * 64) / 256, 3), 256>>>(query, key, value, Aq, Ak, Av);

    gemm_tc_qkv<<<dim3(4, 64, 3), 256, GEMM_SMEM>>>(Aq, Ak, Av, Wp,
                                                    bq, bk, bv, Qb, Kb, Vb);

    pack_k16_kernel<<<(NBH * S_LEN * 32) / 256, 256>>>(Kb, Kpp);
    pack_v16_kernel<<<(NBH * 32 * 32 * 64) / 256, 256>>>(Vb, Vpp);

    dim3 attn_grid(S_LEN / 128, NHEADS, BATCH);   // (16, 8, 4)
    attn_mma_kernel<<<attn_grid, 256, ATTN_SMEM>>>(Qb, Kpp, Vpp, MBp);

    gemm_tc_one<<<dim3(4, 64), 256, GEMM_SMEM>>>(Op, Wp + (size_t)3 * 131072, bo, out);
}

// round 12
// speedup vs baseline: 4.0440x; 1.1825x over previous
#include <cuda_runtime.h>
#include <cuda_bf16.h>
#include <cuda_fp16.h>
#include <cstdint>
#include <math.h>

// Problem constants
#define BATCH   4
#define S_LEN   2048
#define DMODEL  256
#define NHEADS  8
#define HD      32
#define M_ROWS  (BATCH * S_LEN)   // 8192
#define MWORDS  (S_LEN / 32)      // 64 mask words per row
#define NBH     (BATCH * NHEADS)  // 32

// Scratch (device globals: allocation-free per harness rules)
__device__ float          g_Q[M_ROWS * DMODEL];
__device__ float          g_K[M_ROWS * DMODEL];
__device__ float          g_V[M_ROWS * DMODEL];
__device__ unsigned       g_MB[BATCH * S_LEN * MWORDS];        // packed mask bits
__device__ __half         g_Kp16[(size_t)NBH * S_LEN * 32];    // attn K fp16, swizzled 64B rows
__device__ __half         g_Vp16[(size_t)NBH * 32 * 2048];     // attn V^T fp16, 4KB/tile swizzled
// GEMM operand packs: A-format [blk 0..7][row][64 bf16], SW128 swizzled per row
__device__ __nv_bfloat16  g_Aq[(size_t)8 * M_ROWS * 64];
__device__ __nv_bfloat16  g_Ak[(size_t)8 * M_ROWS * 64];
__device__ __nv_bfloat16  g_Av[(size_t)8 * M_ROWS * 64];
__device__ __nv_bfloat16  g_Op[(size_t)8 * M_ROWS * 64];       // attn output, packed directly
__device__ __nv_bfloat16  g_Wp[(size_t)4 * 8 * 256 * 64];      // weights q,k,v,o

// ---------------------------------------------------------------------------
// Helpers
// ---------------------------------------------------------------------------
__device__ __forceinline__ uint32_t smem_u32(const void* p) {
    uint32_t a;
    asm("{ .reg .u64 t; cvta.to.shared.u64 t, %1; cvt.u32.u64 %0, t; }" : "=r"(a) : "l"(p));
    return a;
}
__device__ __forceinline__ float ex2(float x) {
    float y; asm("ex2.approx.f32 %0, %1;" : "=f"(y) : "f"(x)); return y;
}
// pack two fp32 -> bf16x2 (lo = p0, hi = p1)
#define CVT_BF16X2(result, p0, p1) \
    asm("cvt.rn.satfinite.bf16x2.f32 %0, %1, %2;" : "=r"(result) : "f"(p1), "f"(p0))
// pack two fp32 -> f16x2 (lo = p0, hi = p1)
#define CVT_F16X2(result, p0, p1) \
    asm("cvt.rn.f16x2.f32 %0, %1, %2;" : "=r"(result) : "f"(p1), "f"(p0))

__device__ __forceinline__ void ldm_x4(uint32_t (&r)[4], uint32_t addr) {
    asm volatile("ldmatrix.sync.aligned.m8n8.x4.shared.b16 {%0,%1,%2,%3}, [%4];"
                 : "=r"(r[0]), "=r"(r[1]), "=r"(r[2]), "=r"(r[3]) : "r"(addr));
}
__device__ __forceinline__ void mma_bf16(float (&d)[4], const uint32_t* a, const uint32_t* b) {
    asm volatile("mma.sync.aligned.m16n8k16.row.col.f32.bf16.bf16.f32 "
                 "{%0,%1,%2,%3}, {%4,%5,%6,%7}, {%8,%9}, {%0,%1,%2,%3};"
                 : "+f"(d[0]), "+f"(d[1]), "+f"(d[2]), "+f"(d[3])
                 : "r"(a[0]), "r"(a[1]), "r"(a[2]), "r"(a[3]), "r"(b[0]), "r"(b[1]));
}
__device__ __forceinline__ void mma_f16(float (&d)[4], const uint32_t* a, const uint32_t* b) {
    asm volatile("mma.sync.aligned.m16n8k16.row.col.f32.f16.f16.f32 "
                 "{%0,%1,%2,%3}, {%4,%5,%6,%7}, {%8,%9}, {%0,%1,%2,%3};"
                 : "+f"(d[0]), "+f"(d[1]), "+f"(d[2]), "+f"(d[3])
                 : "r"(a[0]), "r"(a[1]), "r"(a[2]), "r"(a[3]), "r"(b[0]), "r"(b[1]));
}

#define CP16(dst, src) \
    asm volatile("cp.async.cg.shared.global [%0], [%1], 16;" :: "r"(dst), "l"(src))
#define CP_COMMIT() asm volatile("cp.async.commit_group;" ::: "memory")
#define CP_WAIT0()  asm volatile("cp.async.wait_group 0;" ::: "memory")

// ---------------------------------------------------------------------------
// Mask bit-pack v2: one thread = 8 elements (two int4 loads -> one byte).
// Byte k, bit b <-> element 8k+b: identical memory image to u32-word packing.
// ---------------------------------------------------------------------------
__global__ __launch_bounds__(256) void pack_mask_kernel(
    const int4* __restrict__ mask, unsigned char* __restrict__ bits)
{
    int idx = blockIdx.x * 256 + threadIdx.x;
    int4 a = mask[idx * 2];
    int4 b = mask[idx * 2 + 1];
    unsigned byte = (unsigned)(a.x != 0)
                  | ((unsigned)(a.y != 0) << 1)
                  | ((unsigned)(a.z != 0) << 2)
                  | ((unsigned)(a.w != 0) << 3)
                  | ((unsigned)(b.x != 0) << 4)
                  | ((unsigned)(b.y != 0) << 5)
                  | ((unsigned)(b.z != 0) << 6)
                  | ((unsigned)(b.w != 0) << 7);
    bits[idx] = (unsigned char)byte;
}

// ---------------------------------------------------------------------------
// Pack activations (q/k/v inputs) into GEMM A-format: [blk][m][64], swizzled
// ---------------------------------------------------------------------------
__global__ __launch_bounds__(256) void pack_a3_kernel(
    const float* __restrict__ q, const float* __restrict__ k, const float* __restrict__ v,
    __nv_bfloat16* __restrict__ Aq, __nv_bfloat16* __restrict__ Ak, __nv_bfloat16* __restrict__ Av)
{
    const float* src; __nv_bfloat16* dst;
    if (blockIdx.y == 0)      { src = q; dst = Aq; }
    else if (blockIdx.y == 1) { src = k; dst = Ak; }
    else                      { src = v; dst = Av; }
    int idx = blockIdx.x * 256 + threadIdx.x;     // 8 * 8192 * 64
    int c   = idx & 63;
    int m   = (idx >> 6) & (M_ROWS - 1);
    int blk = idx >> 19;
    int d = blk * 32 + (c & 31);
    float val = src[(size_t)m * DMODEL + d];
    __nv_bfloat16 hi = __float2bfloat16(val);
    __nv_bfloat16 out = (c < 32) ? hi : __float2bfloat16(val - __bfloat162float(hi));
    dst[(((size_t)blk * M_ROWS + m) << 6) + (c ^ ((m & 7) << 3))] = out;
}

// ---------------------------------------------------------------------------
// Pack all 4 weight matrices: [w][blk][n][64], swizzled
// ---------------------------------------------------------------------------
__global__ __launch_bounds__(256) void pack_w_kernel(
    const float* __restrict__ Wq, const float* __restrict__ Wk,
    const float* __restrict__ Wv, const float* __restrict__ Wo,
    __nv_bfloat16* __restrict__ Wp)
{
    int idx = blockIdx.x * 256 + threadIdx.x;     // 4 * 8 * 256 * 64
    int c   = idx & 63;
    int n   = (idx >> 6) & 255;
    int blk = (idx >> 14) & 7;
    int w   = idx >> 17;
    const float* W = (w == 0) ? Wq : (w == 1) ? Wk : (w == 2) ? Wv : Wo;
    int d = blk * 32 + (c & 31);
    float val = W[(size_t)n * DMODEL + d];
    __nv_bfloat16 hi = __float2bfloat16(val);
    __nv_bfloat16 out = (c < 32) ? hi : __float2bfloat16(val - __bfloat162float(hi));
    Wp[(((size_t)(w * 8 + blk) * 256 + n) << 6) + (c ^ ((n & 7) << 3))] = out;
}

// ---------------------------------------------------------------------------
// K pack (fp16 single image): per (b,h,s): 32 fp16 = 64B row,
// swizzle chunk (c>>3) ^ ((s>>1)&3)
// ---------------------------------------------------------------------------
__global__ __launch_bounds__(256) void pack_k16_kernel(
    const float* __restrict__ K, __half* __restrict__ Kp)
{
    int idx = blockIdx.x * 256 + threadIdx.x;      // NBH*2048*32
    int c = idx & 31;
    int row = idx >> 5;
    int s = row & (S_LEN - 1);
    int bh = row >> 11;
    int b = bh >> 3, h = bh & 7;
    float v = K[(size_t)(b * S_LEN + s) * DMODEL + h * HD + c];
    Kp[(size_t)row * 32 + (c ^ (((s >> 1) & 3) << 3))] = __float2half_rn(v);
}

// ---------------------------------------------------------------------------
// V pack (fp16 single image): per (b,h,ktile): V^T 32d x 64key, 128B rows
// ---------------------------------------------------------------------------
__global__ __launch_bounds__(256) void pack_v16_kernel(
    const float* __restrict__ V, __half* __restrict__ Vp)
{
    int idx = blockIdx.x * 256 + threadIdx.x;      // NBH*32*32*64
    int key = idx & 63;
    int d   = (idx >> 6) & 31;
    int t   = (idx >> 11) & 31;
    int bh  = idx >> 16;
    int b = bh >> 3, h = bh & 7;
    float v = V[(size_t)(b * S_LEN + t * 64 + key) * DMODEL + h * HD + d];
    Vp[(size_t)bh * 65536 + t * 2048 + d * 64 + (key ^ ((d & 7) << 3))] = __float2half_rn(v);
}

// ---------------------------------------------------------------------------
// Tensor-core GEMM: C[M,256] = A[M,256] @ W^T + bias, bf16 hi/lo 3-term.
// ---------------------------------------------------------------------------
#define GEMM_SMEM 98304
#define CPG_WAIT1() asm volatile("cp.async.wait_group 1;" ::: "memory")

__device__ __forceinline__ void gemm_tc_body(
    const __nv_bfloat16* __restrict__ Ap, const __nv_bfloat16* __restrict__ Wp,
    const float* __restrict__ bias, float* __restrict__ C, char* smem)
{
    const uint32_t sb = smem_u32(smem);
    const int tid = threadIdx.x, lane = tid & 31, wid = tid >> 5;
    const int n0 = blockIdx.x * 64, m0 = blockIdx.y * 128;
    const char* Ab = (const char*)Ap;
    const char* Wb = (const char*)Wp;

    auto stage = [&](int t, uint32_t buf) {
        #pragma unroll
        for (int i = 0; i < 8; i++) {
            int g = i * 256 + tid;
            int blk = g >> 10, row = (g >> 3) & 127, ch = g & 7;
            CP16(sb + buf + blk * 16384 + row * 128 + ch * 16,
                 Ab + ((size_t)(t * 2 + blk) * M_ROWS + m0 + row) * 128 + ch * 16);
        }
        #pragma unroll
        for (int i = 0; i < 4; i++) {
            int g = i * 256 + tid;
            int blk = g >> 9, row = (g >> 3) & 63, ch = g & 7;
            CP16(sb + buf + 32768 + blk * 8192 + row * 128 + ch * 16,
                 Wb + ((size_t)(t * 2 + blk) * 256 + n0 + row) * 128 + ch * 16);
        }
        CP_COMMIT();
    };

    stage(0, 0);

    float c[8][4];
    #pragma unroll
    for (int i = 0; i < 8; i++)
        #pragma unroll
        for (int j = 0; j < 4; j++) c[i][j] = 0.f;

    const int m_off = (lane & 7) + ((lane >> 3) & 1) * 8;
    const int coff  = (lane >> 4) & 1;
    const int m = wid * 16 + m_off;
    const int kb_row = (lane & 7) + ((lane >> 4) & 1) * 8;
    const int kb_c   = (lane >> 3) & 1;

    for (int t = 0; t < 4; t++) {
        if (t < 3) { stage(t + 1, ((t + 1) & 1) * 49152); CPG_WAIT1(); }
        else       { CP_WAIT0(); }
        __syncthreads();

        const uint32_t abase = sb + (t & 1) * 49152;
        const uint32_t wbase = abase + 32768;

        #pragma unroll
        for (int k16 = 0; k16 < 4; k16++) {
            const int ablk = k16 >> 1;
            const int ch = 2 * (k16 & 1) + coff;
            const uint32_t arow = abase + ablk * 16384 + m * 128;
            uint32_t afh[4], afl[4];
            ldm_x4(afh, arow + (((ch)     ^ (m & 7)) << 4));
            ldm_x4(afl, arow + (((ch + 4) ^ (m & 7)) << 4));
            #pragma unroll
            for (int np = 0; np < 4; np++) {
                const int n = np * 16 + kb_row;
                const uint32_t wrow = wbase + ablk * 8192 + n * 128;
                const int wch = 2 * (k16 & 1) + kb_c;
                uint32_t bhf[4], blf[4];
                ldm_x4(bhf, wrow + (((wch)     ^ (n & 7)) << 4));
                mma_bf16(c[2 * np],     afh, bhf + 0);
                mma_bf16(c[2 * np + 1], afh, bhf + 2);
                mma_bf16(c[2 * np],     afl, bhf + 0);
                mma_bf16(c[2 * np + 1], afl, bhf + 2);
                ldm_x4(blf, wrow + (((wch + 4) ^ (n & 7)) << 4));
                mma_bf16(c[2 * np],     afh, blf + 0);
                mma_bf16(c[2 * np + 1], afh, blf + 2);
            }
        }
        __syncthreads();
    }

    const int r0 = m0 + wid * 16 + (lane >> 2);
    #pragma unroll
    for (int np = 0; np < 4; np++) {
        #pragma unroll
        for (int half = 0; half < 2; half++) {
            const int col = n0 + np * 16 + half * 8 + (lane & 3) * 2;
            const float b0 = bias[col], b1 = bias[col + 1];
            float* p0 = C + (size_t)r0 * DMODEL + col;
            *(float2*)p0 = make_float2(c[2 * np + half][0] + b0, c[2 * np + half][1] + b1);
            *(float2*)(p0 + 8 * DMODEL) = make_float2(c[2 * np + half][2] + b0, c[2 * np + half][3] + b1);
        }
    }
}

__global__ __launch_bounds__(256, 2) void gemm_tc_qkv(
    const __nv_bfloat16* __restrict__ Aq, const __nv_bfloat16* __restrict__ Ak,
    const __nv_bfloat16* __restrict__ Av, const __nv_bfloat16* __restrict__ Wp,
    const float* __restrict__ bq, const float* __restrict__ bk, const float* __restrict__ bv,
    float* __restrict__ Qo, float* __restrict__ Ko, float* __restrict__ Vo)
{
    extern __shared__ char smem[];
    const __nv_bfloat16* A; const __nv_bfloat16* W; const float* b; float* C;
    if (blockIdx.z == 0)      { A = Aq; W = Wp;                       b = bq; C = Qo; }
    else if (blockIdx.z == 1) { A = Ak; W = Wp + (size_t)1 * 131072;  b = bk; C = Ko; }
    else                      { A = Av; W = Wp + (size_t)2 * 131072;  b = bv; C = Vo; }
    gemm_tc_body(A, W, b, C, smem);
}

__global__ __launch_bounds__(256, 2) void gemm_tc_one(
    const __nv_bfloat16* __restrict__ Ap, const __nv_bfloat16* __restrict__ Wp,
    const float* __restrict__ bias, float* __restrict__ C)
{
    extern __shared__ char smem[];
    gemm_tc_body(Ap, Wp, bias, C, smem);
}

// ---------------------------------------------------------------------------
// fp16 single-pass mma flash attention, 128-key iterations (2 x 64 subtiles),
// single __syncthreads per iteration (WAIT0 -> sync -> prefetch -> compute).
// smem: KV double buffer [2][16KB] at 0 (K 8KB | V 8KB); Q fp16 at 32KB.
// ---------------------------------------------------------------------------
#define SM_KV 0
#define SM_Q  32768
#define ATTN_SMEM 40960

__global__ __launch_bounds__(256, 2) void attn_mma_kernel(
    const float* __restrict__ Q, const __half* __restrict__ Kp,
    const __half* __restrict__ Vp, const unsigned* __restrict__ mbits)
{
    extern __shared__ char smem[];
    const uint32_t sb = smem_u32(smem);
    const int tid = threadIdx.x;
    const int lane = tid & 31, wid = tid >> 5;
    const int b = blockIdx.z, h = blockIdx.y;
    const int q0 = blockIdx.x * 128;
    const int bh = b * NHEADS + h;
    const float SC = 0.17677669529663687f * 1.4426950408889634f; // 1/sqrt(32)*log2e

    const char* ksrc = (const char*)(Kp + (size_t)bh * 65536);
    const char* vsrc = (const char*)(Vp + (size_t)bh * 65536);

    // ---- prefetch iteration 0 (K 8KB + V 8KB) ----
    {
        uint32_t d0 = sb + SM_KV;
        CP16(d0 + tid * 16,                ksrc + tid * 16);
        CP16(d0 + (tid + 256) * 16,        ksrc + (tid + 256) * 16);
        CP16(d0 + 8192 + tid * 16,         vsrc + tid * 16);
        CP16(d0 + 8192 + (tid + 256) * 16, vsrc + (tid + 256) * 16);
        CP_COMMIT();
    }

    // ---- Q staging: fp16 single image, 64B rows, chunk swizzle (m>>1)&3 ----
    {
        const int m = tid >> 1;
        const float* qp = Q + ((size_t)(b * S_LEN + q0 + m)) * DMODEL + h * HD + (tid & 1) * 16;
        const int swq = (m >> 1) & 3;
        #pragma unroll
        for (int c4 = 0; c4 < 4; c4++) {
            float4 v4 = *(const float4*)&qp[c4 * 4];
            uint32_t p0, p1;
            CVT_F16X2(p0, v4.x * SC, v4.y * SC);
            CVT_F16X2(p1, v4.z * SC, v4.w * SC);
            const int c0 = (tid & 1) * 16 + c4 * 4;
            char* dst = smem + SM_Q + m * 64 + (((c0 >> 3) ^ swq) << 4) + (c0 & 7) * 2;
            *(uint32_t*)dst = p0;
            *(uint32_t*)(dst + 4) = p1;
        }
    }
    __syncthreads();

    // ---- Q A-fragments (fp16, single image) ----
    uint32_t qf[2][4];
    {
        const int m_off = (lane & 7) + ((lane >> 3) & 1) * 8;
        const int coff  = (lane >> 4) & 1;
        const int m = wid * 16 + m_off;
        const uint32_t qrow = sb + SM_Q + m * 64;
        const int swq = (m >> 1) & 3;
        #pragma unroll
        for (int k16 = 0; k16 < 2; k16++) {
            int ch = 2 * k16 + coff;
            ldm_x4(qf[k16], qrow + ((ch ^ swq) << 4));
        }
    }

    const int kb_row = (lane & 7) + ((lane >> 4) & 1) * 8;
    const int kb_c   = (lane >> 3) & 1;

    const unsigned* mb0 = mbits + (size_t)(b * S_LEN + q0 + wid * 16 + (lane >> 2)) * MWORDS;
    const unsigned* mb1 = mb0 + 8 * MWORDS;

    float l0 = 0.f, l1 = 0.f;
    float o[4][4];
    #pragma unroll
    for (int i = 0; i < 4; i++)
        #pragma unroll
        for (int j = 0; j < 4; j++) o[i][j] = 0.f;

    for (int it = 0; it < 16; it++) {
        // tile it arrived; all warps done with iteration it-1
        CP_WAIT0();
        __syncthreads();

        // prefetch it+1 into the other slot (safe: slot last read at it-1)
        if (it < 15) {
            uint32_t d1 = sb + SM_KV + ((it + 1) & 1) * 16384;
            const char* ks = ksrc + (size_t)(it + 1) * 8192;
            const char* vs = vsrc + (size_t)(it + 1) * 8192;
            CP16(d1 + tid * 16,                ks + tid * 16);
            CP16(d1 + (tid + 256) * 16,        ks + (tid + 256) * 16);
            CP16(d1 + 8192 + tid * 16,         vs + tid * 16);
            CP16(d1 + 8192 + (tid + 256) * 16, vs + (tid + 256) * 16);
            CP_COMMIT();
        }

        const uint32_t slot = sb + SM_KV + (it & 1) * 16384;

        #pragma unroll
        for (int sub = 0; sub < 2; sub++) {
            const uint32_t kbase = slot + sub * 4096;
            const uint32_t vbase = slot + 8192 + sub * 4096;

            // ---- QK^T (fp16): 8 ldm + 16 mma ----
            float c[8][4];
            #pragma unroll
            for (int i = 0; i < 8; i++)
                #pragma unroll
                for (int j = 0; j < 4; j++) c[i][j] = 0.f;

            #pragma unroll
            for (int k16 = 0; k16 < 2; k16++) {
                #pragma unroll
                for (int np = 0; np < 4; np++) {
                    const int key = np * 16 + kb_row;
                    const int ch  = 2 * k16 + kb_c;
                    uint32_t bf[4];
                    ldm_x4(bf, kbase + key * 64 + ((ch ^ ((key >> 1) & 3)) << 4));
                    mma_f16(c[2 * np],     qf[k16], bf + 0);
                    mma_f16(c[2 * np + 1], qf[k16], bf + 2);
                }
            }

            // ---- softmax -> P fp16 fragments ----
            const uint64_t mw0 = *(const uint64_t*)(mb0 + it * 4 + sub * 2);
            const uint64_t mw1 = *(const uint64_t*)(mb1 + it * 4 + sub * 2);
            uint32_t ap[4][4];
            #pragma unroll
            for (int jj = 0; jj < 4; jj++) {
                #pragma unroll
                for (int half = 0; half < 2; half++) {
                    const int j = 2 * jj + half;
                    const int colb = j * 8 + (lane & 3) * 2;
                    float p0 = ((mw0 >> colb)       & 1) ? ex2(c[j][0]) : 0.f;
                    float p1 = ((mw0 >> (colb + 1)) & 1) ? ex2(c[j][1]) : 0.f;
                    float p2 = ((mw1 >> colb)       & 1) ? ex2(c[j][2]) : 0.f;
                    float p3 = ((mw1 >> (colb + 1)) & 1) ? ex2(c[j][3]) : 0.f;
                    l0 += p0 + p1; l1 += p2 + p3;
                    CVT_F16X2(ap[jj][half * 2],     p0, p1);
                    CVT_F16X2(ap[jj][half * 2 + 1], p2, p3);
                }
            }

            // ---- PV (fp16): 8 ldm + 16 mma ----
            #pragma unroll
            for (int k16 = 0; k16 < 4; k16++) {
                #pragma unroll
                for (int np = 0; np < 2; np++) {
                    const int d  = np * 16 + kb_row;
                    const int ch = 2 * k16 + kb_c;
                    uint32_t bv[4];
                    ldm_x4(bv, vbase + d * 128 + ((ch ^ (d & 7)) << 4));
                    mma_f16(o[2 * np],     ap[k16], bv + 0);
                    mma_f16(o[2 * np + 1], ap[k16], bv + 2);
                }
            }
        }
    }

    // ---- finalize: normalize and write packed bf16 hi/lo GEMM-A format ----
    l0 += __shfl_xor_sync(0xffffffffu, l0, 1);
    l0 += __shfl_xor_sync(0xffffffffu, l0, 2);
    l1 += __shfl_xor_sync(0xffffffffu, l1, 1);
    l1 += __shfl_xor_sync(0xffffffffu, l1, 2);
    const float inv0 = 1.f / l0, inv1 = 1.f / l1;

    const int r0g = q0 + wid * 16 + (lane >> 2);
    const int r1g = r0g + 8;
    uint32_t* Op32 = (uint32_t*)g_Op;
    const size_t base0 = ((size_t)h * M_ROWS + b * S_LEN + r0g) * 32;
    const size_t base1 = ((size_t)h * M_ROWS + b * S_LEN + r1g) * 32;
    const int sw0 = (r0g & 7) << 3;
    const int sw1 = (r1g & 7) << 3;
    #pragma unroll
    for (int j = 0; j < 4; j++) {
        const int d = j * 8 + (lane & 3) * 2;
        float v0 = o[j][0] * inv0, v1 = o[j][1] * inv0;
        float v2 = o[j][2] * inv1, v3 = o[j][3] * inv1;
        uint32_t h01, h23;
        CVT_BF16X2(h01, v0, v1);
        CVT_BF16X2(h23, v2, v3);
        float r0l = v0 - __uint_as_float(h01 << 16);
        float r1l = v1 - __uint_as_float(h01 & 0xffff0000u);
        float r2l = v2 - __uint_as_float(h23 << 16);
        float r3l = v3 - __uint_as_float(h23 & 0xffff0000u);
        uint32_t l01, l23;
        CVT_BF16X2(l01, r0l, r1l);
        CVT_BF16X2(l23, r2l, r3l);
        Op32[base0 + (((d)      ^ sw0) >> 1)] = h01;
        Op32[base0 + (((32 + d) ^ sw0) >> 1)] = l01;
        Op32[base1 + (((d)      ^ sw1) >> 1)] = h23;
        Op32[base1 + (((32 + d) ^ sw1) >> 1)] = l23;
    }
}

// ---------------------------------------------------------------------------
// Launch
// ---------------------------------------------------------------------------
extern "C" void kernel_launch(void* const* d_in, const int* in_sizes, int n_in,
                              void* d_out, int out_size)
{
    const float* query = (const float*)d_in[0];
    const float* key   = (const float*)d_in[1];
    const float* value = (const float*)d_in[2];
    const int*   mask  = (const int*)  d_in[3];
    const float* Wq = (const float*)d_in[4];
    const float* bq = (const float*)d_in[5];
    const float* Wk = (const float*)d_in[6];
    const float* bk = (const float*)d_in[7];
    const float* Wv = (const float*)d_in[8];
    const float* bv = (const float*)d_in[9];
    const float* Wo = (const float*)d_in[10];
    const float* bo = (const float*)d_in[11];
    float* out = (float*)d_out;

    float *Qb, *Kb, *Vb;
    unsigned* MBp;
    __half *Kpp, *Vpp;
    __nv_bfloat16 *Aq, *Ak, *Av, *Op, *Wp;
    cudaGetSymbolAddress((void**)&Qb, g_Q);
    cudaGetSymbolAddress((void**)&Kb, g_K);
    cudaGetSymbolAddress((void**)&Vb, g_V);
    cudaGetSymbolAddress((void**)&MBp, g_MB);
    cudaGetSymbolAddress((void**)&Kpp, g_Kp16);
    cudaGetSymbolAddress((void**)&Vpp, g_Vp16);
    cudaGetSymbolAddress((void**)&Aq, g_Aq);
    cudaGetSymbolAddress((void**)&Ak, g_Ak);
    cudaGetSymbolAddress((void**)&Av, g_Av);
    cudaGetSymbolAddress((void**)&Op, g_Op);
    cudaGetSymbolAddress((void**)&Wp, g_Wp);

    cudaFuncSetAttribute(attn_mma_kernel, cudaFuncAttributeMaxDynamicSharedMemorySize, ATTN_SMEM);
    cudaFuncSetAttribute(gemm_tc_qkv, cudaFuncAttributeMaxDynamicSharedMemorySize, GEMM_SMEM);
    cudaFuncSetAttribute(gemm_tc_one, cudaFuncAttributeMaxDynamicSharedMemorySize, GEMM_SMEM);

    pack_mask_kernel<<<(BATCH * S_LEN * S_LEN) / 8 / 256, 256>>>(
        (const int4*)mask, (unsigned char*)MBp);
    pack_w_kernel<<<(4 * 8 * 256 * 64) / 256, 256>>>(Wq, Wk, Wv, Wo, Wp);
    pack_a3_kernel<<<dim3((8 * M_ROWS * 64) / 256, 3), 256>>>(query, key, value, Aq, Ak, Av);

    gemm_tc_qkv<<<dim3(4, 64, 3), 256, GEMM_SMEM>>>(Aq, Ak, Av, Wp,
                                                    bq, bk, bv, Qb, Kb, Vb);

    pack_k16_kernel<<<(NBH * S_LEN * 32) / 256, 256>>>(Kb, Kpp);
    pack_v16_kernel<<<(NBH * 32 * 32 * 64) / 256, 256>>>(Vb, Vpp);

    dim3 attn_grid(S_LEN / 128, NHEADS, BATCH);   // (16, 8, 4)
    attn_mma_kernel<<<attn_grid, 256, ATTN_SMEM>>>(Qb, Kpp, Vpp, MBp);

    gemm_tc_one<<<dim3(4, 64), 256, GEMM_SMEM>>>(Op, Wp + (size_t)3 * 131072, bo, out);
}

// round 13
// speedup vs baseline: 4.0488x; 1.0012x over previous
#include <cuda_runtime.h>
#include <cuda_bf16.h>
#include <cuda_fp16.h>
#include <cstdint>
#include <math.h>

// Problem constants
#define BATCH   4
#define S_LEN   2048
#define DMODEL  256
#define NHEADS  8
#define HD      32
#define M_ROWS  (BATCH * S_LEN)   // 8192
#define MWORDS  (S_LEN / 32)      // 64 mask words per row
#define NBH     (BATCH * NHEADS)  // 32

// Scratch (device globals: allocation-free per harness rules)
__device__ float          g_Q[M_ROWS * DMODEL];
__device__ float          g_K[M_ROWS * DMODEL];
__device__ float          g_V[M_ROWS * DMODEL];
__device__ unsigned       g_MB[BATCH * S_LEN * MWORDS];        // packed mask bits
__device__ __half         g_Kp16[(size_t)NBH * S_LEN * 32];    // attn K fp16, swizzled 64B rows
__device__ __half         g_Vp16[(size_t)NBH * 32 * 2048];     // attn V^T fp16, 4KB/tile swizzled
// GEMM operand packs: A-format [blk 0..7][row][64 bf16], SW128 swizzled per row
__device__ __nv_bfloat16  g_Aq[(size_t)8 * M_ROWS * 64];
__device__ __nv_bfloat16  g_Ak[(size_t)8 * M_ROWS * 64];
__device__ __nv_bfloat16  g_Av[(size_t)8 * M_ROWS * 64];
__device__ __nv_bfloat16  g_Op[(size_t)8 * M_ROWS * 64];       // attn output, packed directly
__device__ __nv_bfloat16  g_Wp[(size_t)4 * 8 * 256 * 64];      // weights q,k,v,o

// ---------------------------------------------------------------------------
// Helpers
// ---------------------------------------------------------------------------
__device__ __forceinline__ uint32_t smem_u32(const void* p) {
    uint32_t a;
    asm("{ .reg .u64 t; cvta.to.shared.u64 t, %1; cvt.u32.u64 %0, t; }" : "=r"(a) : "l"(p));
    return a;
}
__device__ __forceinline__ float ex2(float x) {
    float y; asm("ex2.approx.f32 %0, %1;" : "=f"(y) : "f"(x)); return y;
}
// pack two fp32 -> bf16x2 (lo = p0, hi = p1)
#define CVT_BF16X2(result, p0, p1) \
    asm("cvt.rn.satfinite.bf16x2.f32 %0, %1, %2;" : "=r"(result) : "f"(p1), "f"(p0))
// pack two fp32 -> f16x2 (lo = p0, hi = p1)
#define CVT_F16X2(result, p0, p1) \
    asm("cvt.rn.f16x2.f32 %0, %1, %2;" : "=r"(result) : "f"(p1), "f"(p0))

__device__ __forceinline__ void ldm_x4(uint32_t (&r)[4], uint32_t addr) {
    asm volatile("ldmatrix.sync.aligned.m8n8.x4.shared.b16 {%0,%1,%2,%3}, [%4];"
                 : "=r"(r[0]), "=r"(r[1]), "=r"(r[2]), "=r"(r[3]) : "r"(addr));
}
__device__ __forceinline__ void mma_bf16(float (&d)[4], const uint32_t* a, const uint32_t* b) {
    asm volatile("mma.sync.aligned.m16n8k16.row.col.f32.bf16.bf16.f32 "
                 "{%0,%1,%2,%3}, {%4,%5,%6,%7}, {%8,%9}, {%0,%1,%2,%3};"
                 : "+f"(d[0]), "+f"(d[1]), "+f"(d[2]), "+f"(d[3])
                 : "r"(a[0]), "r"(a[1]), "r"(a[2]), "r"(a[3]), "r"(b[0]), "r"(b[1]));
}
__device__ __forceinline__ void mma_f16(float (&d)[4], const uint32_t* a, const uint32_t* b) {
    asm volatile("mma.sync.aligned.m16n8k16.row.col.f32.f16.f16.f32 "
                 "{%0,%1,%2,%3}, {%4,%5,%6,%7}, {%8,%9}, {%0,%1,%2,%3};"
                 : "+f"(d[0]), "+f"(d[1]), "+f"(d[2]), "+f"(d[3])
                 : "r"(a[0]), "r"(a[1]), "r"(a[2]), "r"(a[3]), "r"(b[0]), "r"(b[1]));
}

#define CP16(dst, src) \
    asm volatile("cp.async.cg.shared.global [%0], [%1], 16;" :: "r"(dst), "l"(src))
#define CP_COMMIT() asm volatile("cp.async.commit_group;" ::: "memory")
#define CP_WAIT0()  asm volatile("cp.async.wait_group 0;" ::: "memory")

// ---------------------------------------------------------------------------
// Mask bit-pack v2: one thread = 8 elements (two int4 loads -> one byte).
// Byte k, bit b <-> element 8k+b: identical memory image to u32-word packing.
// ---------------------------------------------------------------------------
__global__ __launch_bounds__(256) void pack_mask_kernel(
    const int4* __restrict__ mask, unsigned char* __restrict__ bits)
{
    int idx = blockIdx.x * 256 + threadIdx.x;
    int4 a = mask[idx * 2];
    int4 b = mask[idx * 2 + 1];
    unsigned byte = (unsigned)(a.x != 0)
                  | ((unsigned)(a.y != 0) << 1)
                  | ((unsigned)(a.z != 0) << 2)
                  | ((unsigned)(a.w != 0) << 3)
                  | ((unsigned)(b.x != 0) << 4)
                  | ((unsigned)(b.y != 0) << 5)
                  | ((unsigned)(b.z != 0) << 6)
                  | ((unsigned)(b.w != 0) << 7);
    bits[idx] = (unsigned char)byte;
}

// ---------------------------------------------------------------------------
// Pack activations (q/k/v inputs) into GEMM A-format: [blk][m][64], swizzled
// ---------------------------------------------------------------------------
__global__ __launch_bounds__(256) void pack_a3_kernel(
    const float* __restrict__ q, const float* __restrict__ k, const float* __restrict__ v,
    __nv_bfloat16* __restrict__ Aq, __nv_bfloat16* __restrict__ Ak, __nv_bfloat16* __restrict__ Av)
{
    const float* src; __nv_bfloat16* dst;
    if (blockIdx.y == 0)      { src = q; dst = Aq; }
    else if (blockIdx.y == 1) { src = k; dst = Ak; }
    else                      { src = v; dst = Av; }
    int idx = blockIdx.x * 256 + threadIdx.x;     // 8 * 8192 * 64
    int c   = idx & 63;
    int m   = (idx >> 6) & (M_ROWS - 1);
    int blk = idx >> 19;
    int d = blk * 32 + (c & 31);
    float val = src[(size_t)m * DMODEL + d];
    __nv_bfloat16 hi = __float2bfloat16(val);
    __nv_bfloat16 out = (c < 32) ? hi : __float2bfloat16(val - __bfloat162float(hi));
    dst[(((size_t)blk * M_ROWS + m) << 6) + (c ^ ((m & 7) << 3))] = out;
}

// ---------------------------------------------------------------------------
// Pack all 4 weight matrices: [w][blk][n][64], swizzled
// ---------------------------------------------------------------------------
__global__ __launch_bounds__(256) void pack_w_kernel(
    const float* __restrict__ Wq, const float* __restrict__ Wk,
    const float* __restrict__ Wv, const float* __restrict__ Wo,
    __nv_bfloat16* __restrict__ Wp)
{
    int idx = blockIdx.x * 256 + threadIdx.x;     // 4 * 8 * 256 * 64
    int c   = idx & 63;
    int n   = (idx >> 6) & 255;
    int blk = (idx >> 14) & 7;
    int w   = idx >> 17;
    const float* W = (w == 0) ? Wq : (w == 1) ? Wk : (w == 2) ? Wv : Wo;
    int d = blk * 32 + (c & 31);
    float val = W[(size_t)n * DMODEL + d];
    __nv_bfloat16 hi = __float2bfloat16(val);
    __nv_bfloat16 out = (c < 32) ? hi : __float2bfloat16(val - __bfloat162float(hi));
    Wp[(((size_t)(w * 8 + blk) * 256 + n) << 6) + (c ^ ((n & 7) << 3))] = out;
}

// ---------------------------------------------------------------------------
// K pack (fp16 single image): per (b,h,s): 32 fp16 = 64B row,
// swizzle chunk (c>>3) ^ ((s>>1)&3)
// ---------------------------------------------------------------------------
__global__ __launch_bounds__(256) void pack_k16_kernel(
    const float* __restrict__ K, __half* __restrict__ Kp)
{
    int idx = blockIdx.x * 256 + threadIdx.x;      // NBH*2048*32
    int c = idx & 31;
    int row = idx >> 5;
    int s = row & (S_LEN - 1);
    int bh = row >> 11;
    int b = bh >> 3, h = bh & 7;
    float v = K[(size_t)(b * S_LEN + s) * DMODEL + h * HD + c];
    Kp[(size_t)row * 32 + (c ^ (((s >> 1) & 3) << 3))] = __float2half_rn(v);
}

// ---------------------------------------------------------------------------
// V pack (fp16 single image): per (b,h,ktile): V^T 32d x 64key, 128B rows
// ---------------------------------------------------------------------------
__global__ __launch_bounds__(256) void pack_v16_kernel(
    const float* __restrict__ V, __half* __restrict__ Vp)
{
    int idx = blockIdx.x * 256 + threadIdx.x;      // NBH*32*32*64
    int key = idx & 63;
    int d   = (idx >> 6) & 31;
    int t   = (idx >> 11) & 31;
    int bh  = idx >> 16;
    int b = bh >> 3, h = bh & 7;
    float v = V[(size_t)(b * S_LEN + t * 64 + key) * DMODEL + h * HD + d];
    Vp[(size_t)bh * 65536 + t * 2048 + d * 64 + (key ^ ((d & 7) << 3))] = __float2half_rn(v);
}

// ---------------------------------------------------------------------------
// Tensor-core GEMM: C[M,256] = A[M,256] @ W^T + bias, bf16 hi/lo 3-term.
// ---------------------------------------------------------------------------
#define GEMM_SMEM 98304
#define CPG_WAIT1() asm volatile("cp.async.wait_group 1;" ::: "memory")

__device__ __forceinline__ void gemm_tc_body(
    const __nv_bfloat16* __restrict__ Ap, const __nv_bfloat16* __restrict__ Wp,
    const float* __restrict__ bias, float* __restrict__ C, char* smem)
{
    const uint32_t sb = smem_u32(smem);
    const int tid = threadIdx.x, lane = tid & 31, wid = tid >> 5;
    const int n0 = blockIdx.x * 64, m0 = blockIdx.y * 128;
    const char* Ab = (const char*)Ap;
    const char* Wb = (const char*)Wp;

    auto stage = [&](int t, uint32_t buf) {
        #pragma unroll
        for (int i = 0; i < 8; i++) {
            int g = i * 256 + tid;
            int blk = g >> 10, row = (g >> 3) & 127, ch = g & 7;
            CP16(sb + buf + blk * 16384 + row * 128 + ch * 16,
                 Ab + ((size_t)(t * 2 + blk) * M_ROWS + m0 + row) * 128 + ch * 16);
        }
        #pragma unroll
        for (int i = 0; i < 4; i++) {
            int g = i * 256 + tid;
            int blk = g >> 9, row = (g >> 3) & 63, ch = g & 7;
            CP16(sb + buf + 32768 + blk * 8192 + row * 128 + ch * 16,
                 Wb + ((size_t)(t * 2 + blk) * 256 + n0 + row) * 128 + ch * 16);
        }
        CP_COMMIT();
    };

    stage(0, 0);

    float c[8][4];
    #pragma unroll
    for (int i = 0; i < 8; i++)
        #pragma unroll
        for (int j = 0; j < 4; j++) c[i][j] = 0.f;

    const int m_off = (lane & 7) + ((lane >> 3) & 1) * 8;
    const int coff  = (lane >> 4) & 1;
    const int m = wid * 16 + m_off;
    const int kb_row = (lane & 7) + ((lane >> 4) & 1) * 8;
    const int kb_c   = (lane >> 3) & 1;

    for (int t = 0; t < 4; t++) {
        if (t < 3) { stage(t + 1, ((t + 1) & 1) * 49152); CPG_WAIT1(); }
        else       { CP_WAIT0(); }
        __syncthreads();

        const uint32_t abase = sb + (t & 1) * 49152;
        const uint32_t wbase = abase + 32768;

        #pragma unroll
        for (int k16 = 0; k16 < 4; k16++) {
            const int ablk = k16 >> 1;
            const int ch = 2 * (k16 & 1) + coff;
            const uint32_t arow = abase + ablk * 16384 + m * 128;
            uint32_t afh[4], afl[4];
            ldm_x4(afh, arow + (((ch)     ^ (m & 7)) << 4));
            ldm_x4(afl, arow + (((ch + 4) ^ (m & 7)) << 4));
            #pragma unroll
            for (int np = 0; np < 4; np++) {
                const int n = np * 16 + kb_row;
                const uint32_t wrow = wbase + ablk * 8192 + n * 128;
                const int wch = 2 * (k16 & 1) + kb_c;
                uint32_t bhf[4], blf[4];
                ldm_x4(bhf, wrow + (((wch)     ^ (n & 7)) << 4));
                mma_bf16(c[2 * np],     afh, bhf + 0);
                mma_bf16(c[2 * np + 1], afh, bhf + 2);
                mma_bf16(c[2 * np],     afl, bhf + 0);
                mma_bf16(c[2 * np + 1], afl, bhf + 2);
                ldm_x4(blf, wrow + (((wch + 4) ^ (n & 7)) << 4));
                mma_bf16(c[2 * np],     afh, blf + 0);
                mma_bf16(c[2 * np + 1], afh, blf + 2);
            }
        }
        __syncthreads();
    }

    const int r0 = m0 + wid * 16 + (lane >> 2);
    #pragma unroll
    for (int np = 0; np < 4; np++) {
        #pragma unroll
        for (int half = 0; half < 2; half++) {
            const int col = n0 + np * 16 + half * 8 + (lane & 3) * 2;
            const float b0 = bias[col], b1 = bias[col + 1];
            float* p0 = C + (size_t)r0 * DMODEL + col;
            *(float2*)p0 = make_float2(c[2 * np + half][0] + b0, c[2 * np + half][1] + b1);
            *(float2*)(p0 + 8 * DMODEL) = make_float2(c[2 * np + half][2] + b0, c[2 * np + half][3] + b1);
        }
    }
}

__global__ __launch_bounds__(256, 2) void gemm_tc_qkv(
    const __nv_bfloat16* __restrict__ Aq, const __nv_bfloat16* __restrict__ Ak,
    const __nv_bfloat16* __restrict__ Av, const __nv_bfloat16* __restrict__ Wp,
    const float* __restrict__ bq, const float* __restrict__ bk, const float* __restrict__ bv,
    float* __restrict__ Qo, float* __restrict__ Ko, float* __restrict__ Vo)
{
    extern __shared__ char smem[];
    const __nv_bfloat16* A; const __nv_bfloat16* W; const float* b; float* C;
    if (blockIdx.z == 0)      { A = Aq; W = Wp;                       b = bq; C = Qo; }
    else if (blockIdx.z == 1) { A = Ak; W = Wp + (size_t)1 * 131072;  b = bk; C = Ko; }
    else                      { A = Av; W = Wp + (size_t)2 * 131072;  b = bv; C = Vo; }
    gemm_tc_body(A, W, b, C, smem);
}

__global__ __launch_bounds__(256, 2) void gemm_tc_one(
    const __nv_bfloat16* __restrict__ Ap, const __nv_bfloat16* __restrict__ Wp,
    const float* __restrict__ bias, float* __restrict__ C)
{
    extern __shared__ char smem[];
    gemm_tc_body(Ap, Wp, bias, C, smem);
}

// ---------------------------------------------------------------------------
// fp16 single-pass mma flash attention, 128-key iterations (2 x 64 subtiles),
// single __syncthreads per iteration (WAIT0 -> sync -> prefetch -> compute).
// smem: KV double buffer [2][16KB] at 0 (K 8KB | V 8KB); Q fp16 at 32KB.
// ---------------------------------------------------------------------------
#define SM_KV 0
#define SM_Q  32768
#define ATTN_SMEM 40960

__global__ __launch_bounds__(256, 2) void attn_mma_kernel(
    const float* __restrict__ Q, const __half* __restrict__ Kp,
    const __half* __restrict__ Vp, const unsigned* __restrict__ mbits)
{
    extern __shared__ char smem[];
    const uint32_t sb = smem_u32(smem);
    const int tid = threadIdx.x;
    const int lane = tid & 31, wid = tid >> 5;
    const int b = blockIdx.z, h = blockIdx.y;
    const int q0 = blockIdx.x * 128;
    const int bh = b * NHEADS + h;
    const float SC = 0.17677669529663687f * 1.4426950408889634f; // 1/sqrt(32)*log2e

    const char* ksrc = (const char*)(Kp + (size_t)bh * 65536);
    const char* vsrc = (const char*)(Vp + (size_t)bh * 65536);

    // ---- prefetch iteration 0 (K 8KB + V 8KB) ----
    {
        uint32_t d0 = sb + SM_KV;
        CP16(d0 + tid * 16,                ksrc + tid * 16);
        CP16(d0 + (tid + 256) * 16,        ksrc + (tid + 256) * 16);
        CP16(d0 + 8192 + tid * 16,         vsrc + tid * 16);
        CP16(d0 + 8192 + (tid + 256) * 16, vsrc + (tid + 256) * 16);
        CP_COMMIT();
    }

    // ---- Q staging: fp16 single image, 64B rows, chunk swizzle (m>>1)&3 ----
    {
        const int m = tid >> 1;
        const float* qp = Q + ((size_t)(b * S_LEN + q0 + m)) * DMODEL + h * HD + (tid & 1) * 16;
        const int swq = (m >> 1) & 3;
        #pragma unroll
        for (int c4 = 0; c4 < 4; c4++) {
            float4 v4 = *(const float4*)&qp[c4 * 4];
            uint32_t p0, p1;
            CVT_F16X2(p0, v4.x * SC, v4.y * SC);
            CVT_F16X2(p1, v4.z * SC, v4.w * SC);
            const int c0 = (tid & 1) * 16 + c4 * 4;
            char* dst = smem + SM_Q + m * 64 + (((c0 >> 3) ^ swq) << 4) + (c0 & 7) * 2;
            *(uint32_t*)dst = p0;
            *(uint32_t*)(dst + 4) = p1;
        }
    }
    __syncthreads();

    // ---- Q A-fragments (fp16, single image) ----
    uint32_t qf[2][4];
    {
        const int m_off = (lane & 7) + ((lane >> 3) & 1) * 8;
        const int coff  = (lane >> 4) & 1;
        const int m = wid * 16 + m_off;
        const uint32_t qrow = sb + SM_Q + m * 64;
        const int swq = (m >> 1) & 3;
        #pragma unroll
        for (int k16 = 0; k16 < 2; k16++) {
            int ch = 2 * k16 + coff;
            ldm_x4(qf[k16], qrow + ((ch ^ swq) << 4));
        }
    }

    const int kb_row = (lane & 7) + ((lane >> 4) & 1) * 8;
    const int kb_c   = (lane >> 3) & 1;

    const unsigned* mb0 = mbits + (size_t)(b * S_LEN + q0 + wid * 16 + (lane >> 2)) * MWORDS;
    const unsigned* mb1 = mb0 + 8 * MWORDS;

    float l0 = 0.f, l1 = 0.f;
    float o[4][4];
    #pragma unroll
    for (int i = 0; i < 4; i++)
        #pragma unroll
        for (int j = 0; j < 4; j++) o[i][j] = 0.f;

    for (int it = 0; it < 16; it++) {
        // tile it arrived; all warps done with iteration it-1
        CP_WAIT0();
        __syncthreads();

        // prefetch it+1 into the other slot (safe: slot last read at it-1)
        if (it < 15) {
            uint32_t d1 = sb + SM_KV + ((it + 1) & 1) * 16384;
            const char* ks = ksrc + (size_t)(it + 1) * 8192;
            const char* vs = vsrc + (size_t)(it + 1) * 8192;
            CP16(d1 + tid * 16,                ks + tid * 16);
            CP16(d1 + (tid + 256) * 16,        ks + (tid + 256) * 16);
            CP16(d1 + 8192 + tid * 16,         vs + tid * 16);
            CP16(d1 + 8192 + (tid + 256) * 16, vs + (tid + 256) * 16);
            CP_COMMIT();
        }

        const uint32_t slot = sb + SM_KV + (it & 1) * 16384;

        #pragma unroll
        for (int sub = 0; sub < 2; sub++) {
            const uint32_t kbase = slot + sub * 4096;
            const uint32_t vbase = slot + 8192 + sub * 4096;

            // ---- QK^T (fp16): 8 ldm + 16 mma ----
            float c[8][4];
            #pragma unroll
            for (int i = 0; i < 8; i++)
                #pragma unroll
                for (int j = 0; j < 4; j++) c[i][j] = 0.f;

            #pragma unroll
            for (int k16 = 0; k16 < 2; k16++) {
                #pragma unroll
                for (int np = 0; np < 4; np++) {
                    const int key = np * 16 + kb_row;
                    const int ch  = 2 * k16 + kb_c;
                    uint32_t bf[4];
                    ldm_x4(bf, kbase + key * 64 + ((ch ^ ((key >> 1) & 3)) << 4));
                    mma_f16(c[2 * np],     qf[k16], bf + 0);
                    mma_f16(c[2 * np + 1], qf[k16], bf + 2);
                }
            }

            // ---- softmax -> P fp16 fragments ----
            const uint64_t mw0 = *(const uint64_t*)(mb0 + it * 4 + sub * 2);
            const uint64_t mw1 = *(const uint64_t*)(mb1 + it * 4 + sub * 2);
            uint32_t ap[4][4];
            #pragma unroll
            for (int jj = 0; jj < 4; jj++) {
                #pragma unroll
                for (int half = 0; half < 2; half++) {
                    const int j = 2 * jj + half;
                    const int colb = j * 8 + (lane & 3) * 2;
                    float p0 = ((mw0 >> colb)       & 1) ? ex2(c[j][0]) : 0.f;
                    float p1 = ((mw0 >> (colb + 1)) & 1) ? ex2(c[j][1]) : 0.f;
                    float p2 = ((mw1 >> colb)       & 1) ? ex2(c[j][2]) : 0.f;
                    float p3 = ((mw1 >> (colb + 1)) & 1) ? ex2(c[j][3]) : 0.f;
                    l0 += p0 + p1; l1 += p2 + p3;
                    CVT_F16X2(ap[jj][half * 2],     p0, p1);
                    CVT_F16X2(ap[jj][half * 2 + 1], p2, p3);
                }
            }

            // ---- PV (fp16): 8 ldm + 16 mma ----
            #pragma unroll
            for (int k16 = 0; k16 < 4; k16++) {
                #pragma unroll
                for (int np = 0; np < 2; np++) {
                    const int d  = np * 16 + kb_row;
                    const int ch = 2 * k16 + kb_c;
                    uint32_t bv[4];
                    ldm_x4(bv, vbase + d * 128 + ((ch ^ (d & 7)) << 4));
                    mma_f16(o[2 * np],     ap[k16], bv + 0);
                    mma_f16(o[2 * np + 1], ap[k16], bv + 2);
                }
            }
        }
    }

    // ---- finalize: normalize and write packed bf16 hi/lo GEMM-A format ----
    l0 += __shfl_xor_sync(0xffffffffu, l0, 1);
    l0 += __shfl_xor_sync(0xffffffffu, l0, 2);
    l1 += __shfl_xor_sync(0xffffffffu, l1, 1);
    l1 += __shfl_xor_sync(0xffffffffu, l1, 2);
    const float inv0 = 1.f / l0, inv1 = 1.f / l1;

    const int r0g = q0 + wid * 16 + (lane >> 2);
    const int r1g = r0g + 8;
    uint32_t* Op32 = (uint32_t*)g_Op;
    const size_t base0 = ((size_t)h * M_ROWS + b * S_LEN + r0g) * 32;
    const size_t base1 = ((size_t)h * M_ROWS + b * S_LEN + r1g) * 32;
    const int sw0 = (r0g & 7) << 3;
    const int sw1 = (r1g & 7) << 3;
    #pragma unroll
    for (int j = 0; j < 4; j++) {
        const int d = j * 8 + (lane & 3) * 2;
        float v0 = o[j][0] * inv0, v1 = o[j][1] * inv0;
        float v2 = o[j][2] * inv1, v3 = o[j][3] * inv1;
        uint32_t h01, h23;
        CVT_BF16X2(h01, v0, v1);
        CVT_BF16X2(h23, v2, v3);
        float r0l = v0 - __uint_as_float(h01 << 16);
        float r1l = v1 - __uint_as_float(h01 & 0xffff0000u);
        float r2l = v2 - __uint_as_float(h23 << 16);
        float r3l = v3 - __uint_as_float(h23 & 0xffff0000u);
        uint32_t l01, l23;
        CVT_BF16X2(l01, r0l, r1l);
        CVT_BF16X2(l23, r2l, r3l);
        Op32[base0 + (((d)      ^ sw0) >> 1)] = h01;
        Op32[base0 + (((32 + d) ^ sw0) >> 1)] = l01;
        Op32[base1 + (((d)      ^ sw1) >> 1)] = h23;
        Op32[base1 + (((32 + d) ^ sw1) >> 1)] = l23;
    }
}

// ---------------------------------------------------------------------------
// Launch
// ---------------------------------------------------------------------------
extern "C" void kernel_launch(void* const* d_in, const int* in_sizes, int n_in,
                              void* d_out, int out_size)
{
    const float* query = (const float*)d_in[0];
    const float* key   = (const float*)d_in[1];
    const float* value = (const float*)d_in[2];
    const int*   mask  = (const int*)  d_in[3];
    const float* Wq = (const float*)d_in[4];
    const float* bq = (const float*)d_in[5];
    const float* Wk = (const float*)d_in[6];
    const float* bk = (const float*)d_in[7];
    const float* Wv = (const float*)d_in[8];
    const float* bv = (const float*)d_in[9];
    const float* Wo = (const float*)d_in[10];
    const float* bo = (const float*)d_in[11];
    float* out = (float*)d_out;

    float *Qb, *Kb, *Vb;
    unsigned* MBp;
    __half *Kpp, *Vpp;
    __nv_bfloat16 *Aq, *Ak, *Av, *Op, *Wp;
    cudaGetSymbolAddress((void**)&Qb, g_Q);
    cudaGetSymbolAddress((void**)&Kb, g_K);
    cudaGetSymbolAddress((void**)&Vb, g_V);
    cudaGetSymbolAddress((void**)&MBp, g_MB);
    cudaGetSymbolAddress((void**)&Kpp, g_Kp16);
    cudaGetSymbolAddress((void**)&Vpp, g_Vp16);
    cudaGetSymbolAddress((void**)&Aq, g_Aq);
    cudaGetSymbolAddress((void**)&Ak, g_Ak);
    cudaGetSymbolAddress((void**)&Av, g_Av);
    cudaGetSymbolAddress((void**)&Op, g_Op);
    cudaGetSymbolAddress((void**)&Wp, g_Wp);

    cudaFuncSetAttribute(attn_mma_kernel, cudaFuncAttributeMaxDynamicSharedMemorySize, ATTN_SMEM);
    cudaFuncSetAttribute(gemm_tc_qkv, cudaFuncAttributeMaxDynamicSharedMemorySize, GEMM_SMEM);
    cudaFuncSetAttribute(gemm_tc_one, cudaFuncAttributeMaxDynamicSharedMemorySize, GEMM_SMEM);

    pack_mask_kernel<<<(BATCH * S_LEN * S_LEN) / 8 / 256, 256>>>(
        (const int4*)mask, (unsigned char*)MBp);
    pack_w_kernel<<<(4 * 8 * 256 * 64) / 256, 256>>>(Wq, Wk, Wv, Wo, Wp);
    pack_a3_kernel<<<dim3((8 * M_ROWS * 64) / 256, 3), 256>>>(query, key, value, Aq, Ak, Av);

    gemm_tc_qkv<<<dim3(4, 64, 3), 256, GEMM_SMEM>>>(Aq, Ak, Av, Wp,
                                                    bq, bk, bv, Qb, Kb, Vb);

    pack_k16_kernel<<<(NBH * S_LEN * 32) / 256, 256>>>(Kb, Kpp);
    pack_v16_kernel<<<(NBH * 32 * 32 * 64) / 256, 256>>>(Vb, Vpp);

    dim3 attn_grid(S_LEN / 128, NHEADS, BATCH);   // (16, 8, 4)
    attn_mma_kernel<<<attn_grid, 256, ATTN_SMEM>>>(Qb, Kpp, Vpp, MBp);

    gemm_tc_one<<<dim3(4, 64), 256, GEMM_SMEM>>>(Op, Wp + (size_t)3 * 131072, bo, out);
}

// round 14
// speedup vs baseline: 4.5302x; 1.1189x over previous
#include <cuda_runtime.h>
#include <cuda_bf16.h>
#include <cuda_fp16.h>
#include <cstdint>
#include <math.h>

// Problem constants
#define BATCH   4
#define S_LEN   2048
#define DMODEL  256
#define NHEADS  8
#define HD      32
#define M_ROWS  (BATCH * S_LEN)   // 8192
#define MWORDS  (S_LEN / 32)      // 64 mask words per row
#define NBH     (BATCH * NHEADS)  // 32

// Scratch (device globals: allocation-free per harness rules)
__device__ float          g_V[M_ROWS * DMODEL];
__device__ unsigned       g_MB[BATCH * S_LEN * MWORDS];        // packed mask bits
__device__ __half         g_Qp16[(size_t)NBH * S_LEN * 32];    // attn Q fp16 (SC folded), swizzled 64B rows
__device__ __half         g_Kp16[(size_t)NBH * S_LEN * 32];    // attn K fp16, swizzled 64B rows
__device__ __half         g_Vp16[(size_t)NBH * 32 * 2048];     // attn V^T fp16, 4KB/tile swizzled
// GEMM operand packs: A-format [blk 0..7][row][64 bf16], SW128 swizzled per row
__device__ __nv_bfloat16  g_Aq[(size_t)8 * M_ROWS * 64];
__device__ __nv_bfloat16  g_Ak[(size_t)8 * M_ROWS * 64];
__device__ __nv_bfloat16  g_Av[(size_t)8 * M_ROWS * 64];
__device__ __nv_bfloat16  g_Op[(size_t)8 * M_ROWS * 64];       // attn output, packed directly
__device__ __nv_bfloat16  g_Wp[(size_t)4 * 8 * 256 * 64];      // weights q,k,v,o

#define ATTN_SC (0.17677669529663687f * 1.4426950408889634f)   // 1/sqrt(32)*log2e

// ---------------------------------------------------------------------------
// Helpers
// ---------------------------------------------------------------------------
__device__ __forceinline__ uint32_t smem_u32(const void* p) {
    uint32_t a;
    asm("{ .reg .u64 t; cvta.to.shared.u64 t, %1; cvt.u32.u64 %0, t; }" : "=r"(a) : "l"(p));
    return a;
}
__device__ __forceinline__ float ex2(float x) {
    float y; asm("ex2.approx.f32 %0, %1;" : "=f"(y) : "f"(x)); return y;
}
// pack two fp32 -> bf16x2 (lo = p0, hi = p1)
#define CVT_BF16X2(result, p0, p1) \
    asm("cvt.rn.satfinite.bf16x2.f32 %0, %1, %2;" : "=r"(result) : "f"(p1), "f"(p0))
// pack two fp32 -> f16x2 (lo = p0, hi = p1)
#define CVT_F16X2(result, p0, p1) \
    asm("cvt.rn.f16x2.f32 %0, %1, %2;" : "=r"(result) : "f"(p1), "f"(p0))

__device__ __forceinline__ void ldm_x4(uint32_t (&r)[4], uint32_t addr) {
    asm volatile("ldmatrix.sync.aligned.m8n8.x4.shared.b16 {%0,%1,%2,%3}, [%4];"
                 : "=r"(r[0]), "=r"(r[1]), "=r"(r[2]), "=r"(r[3]) : "r"(addr));
}
__device__ __forceinline__ void mma_bf16(float (&d)[4], const uint32_t* a, const uint32_t* b) {
    asm volatile("mma.sync.aligned.m16n8k16.row.col.f32.bf16.bf16.f32 "
                 "{%0,%1,%2,%3}, {%4,%5,%6,%7}, {%8,%9}, {%0,%1,%2,%3};"
                 : "+f"(d[0]), "+f"(d[1]), "+f"(d[2]), "+f"(d[3])
                 : "r"(a[0]), "r"(a[1]), "r"(a[2]), "r"(a[3]), "r"(b[0]), "r"(b[1]));
}
__device__ __forceinline__ void mma_f16(float (&d)[4], const uint32_t* a, const uint32_t* b) {
    asm volatile("mma.sync.aligned.m16n8k16.row.col.f32.f16.f16.f32 "
                 "{%0,%1,%2,%3}, {%4,%5,%6,%7}, {%8,%9}, {%0,%1,%2,%3};"
                 : "+f"(d[0]), "+f"(d[1]), "+f"(d[2]), "+f"(d[3])
                 : "r"(a[0]), "r"(a[1]), "r"(a[2]), "r"(a[3]), "r"(b[0]), "r"(b[1]));
}

#define CP16(dst, src) \
    asm volatile("cp.async.cg.shared.global [%0], [%1], 16;" :: "r"(dst), "l"(src))
#define CP_COMMIT() asm volatile("cp.async.commit_group;" ::: "memory")
#define CP_WAIT0()  asm volatile("cp.async.wait_group 0;" ::: "memory")
#define CPG_WAIT1() asm volatile("cp.async.wait_group 1;" ::: "memory")

// ---------------------------------------------------------------------------
// Mask bit-pack v2: one thread = 8 elements (two int4 loads -> one byte).
// ---------------------------------------------------------------------------
__global__ __launch_bounds__(256) void pack_mask_kernel(
    const int4* __restrict__ mask, unsigned char* __restrict__ bits)
{
    int idx = blockIdx.x * 256 + threadIdx.x;
    int4 a = mask[idx * 2];
    int4 b = mask[idx * 2 + 1];
    unsigned byte = (unsigned)(a.x != 0)
                  | ((unsigned)(a.y != 0) << 1)
                  | ((unsigned)(a.z != 0) << 2)
                  | ((unsigned)(a.w != 0) << 3)
                  | ((unsigned)(b.x != 0) << 4)
                  | ((unsigned)(b.y != 0) << 5)
                  | ((unsigned)(b.z != 0) << 6)
                  | ((unsigned)(b.w != 0) << 7);
    bits[idx] = (unsigned char)byte;
}

// ---------------------------------------------------------------------------
// pack_a3 v2 (vectorized): one thread = 4 dims -> hi quad + lo quad (uint2 x2)
// ---------------------------------------------------------------------------
__global__ __launch_bounds__(256) void pack_a3_kernel(
    const float* __restrict__ q, const float* __restrict__ k, const float* __restrict__ v,
    __nv_bfloat16* __restrict__ Aq, __nv_bfloat16* __restrict__ Ak, __nv_bfloat16* __restrict__ Av)
{
    const float* src; __nv_bfloat16* dst;
    if (blockIdx.y == 0)      { src = q; dst = Aq; }
    else if (blockIdx.y == 1) { src = k; dst = Ak; }
    else                      { src = v; dst = Av; }
    int idx = blockIdx.x * 256 + threadIdx.x;     // 8 blk * 8192 m * 8 c4
    int c4  = idx & 7;
    int m   = (idx >> 3) & (M_ROWS - 1);
    int blk = (idx >> 16) & 7;
    float4 v4 = *(const float4*)&src[(size_t)m * DMODEL + blk * 32 + c4 * 4];
    uint32_t h0, h1, l0, l1;
    CVT_BF16X2(h0, v4.x, v4.y);
    CVT_BF16X2(h1, v4.z, v4.w);
    float hx = __uint_as_float(h0 << 16), hy = __uint_as_float(h0 & 0xffff0000u);
    float hz = __uint_as_float(h1 << 16), hw = __uint_as_float(h1 & 0xffff0000u);
    CVT_BF16X2(l0, v4.x - hx, v4.y - hy);
    CVT_BF16X2(l1, v4.z - hz, v4.w - hw);
    uint32_t* dp = (uint32_t*)(dst + (((size_t)blk * M_ROWS + m) << 6));
    const int sw = (m & 7) << 3;
    const int chi = (c4 * 4) ^ sw;          // bf16 index of hi quad
    const int clo = (32 + c4 * 4) ^ sw;     // bf16 index of lo quad
    *(uint2*)&dp[chi >> 1] = make_uint2(h0, h1);
    *(uint2*)&dp[clo >> 1] = make_uint2(l0, l1);
}

// ---------------------------------------------------------------------------
// Pack all 4 weight matrices: [w][blk][n][64], swizzled
// ---------------------------------------------------------------------------
__global__ __launch_bounds__(256) void pack_w_kernel(
    const float* __restrict__ Wq, const float* __restrict__ Wk,
    const float* __restrict__ Wv, const float* __restrict__ Wo,
    __nv_bfloat16* __restrict__ Wp)
{
    int idx = blockIdx.x * 256 + threadIdx.x;     // 4 * 8 * 256 * 64
    int c   = idx & 63;
    int n   = (idx >> 6) & 255;
    int blk = (idx >> 14) & 7;
    int w   = idx >> 17;
    const float* W = (w == 0) ? Wq : (w == 1) ? Wk : (w == 2) ? Wv : Wo;
    int d = blk * 32 + (c & 31);
    float val = W[(size_t)n * DMODEL + d];
    __nv_bfloat16 hi = __float2bfloat16(val);
    __nv_bfloat16 out = (c < 32) ? hi : __float2bfloat16(val - __bfloat162float(hi));
    Wp[(((size_t)(w * 8 + blk) * 256 + n) << 6) + (c ^ ((n & 7) << 3))] = out;
}

// ---------------------------------------------------------------------------
// V pack (fp16 single image): per (b,h,ktile): V^T 32d x 64key, 128B rows
// ---------------------------------------------------------------------------
__global__ __launch_bounds__(256) void pack_v16_kernel(
    const float* __restrict__ V, __half* __restrict__ Vp)
{
    int idx = blockIdx.x * 256 + threadIdx.x;      // NBH*32*32*64
    int key = idx & 63;
    int d   = (idx >> 6) & 31;
    int t   = (idx >> 11) & 31;
    int bh  = idx >> 16;
    int b = bh >> 3, h = bh & 7;
    float v = V[(size_t)(b * S_LEN + t * 64 + key) * DMODEL + h * HD + d];
    Vp[(size_t)bh * 65536 + t * 2048 + d * 64 + (key ^ ((d & 7) << 3))] = __float2half_rn(v);
}

// ---------------------------------------------------------------------------
// Tensor-core GEMM: C[M,256] = A[M,256] @ W^T + bias, bf16 hi/lo 3-term.
// MODE 0: fp32 output. MODE 1: fp16 attn-image output ((val+bias)*oscale),
// layout identical to the proven pack_k16: 64B rows, swizzle ((s>>1)&3)<<3.
// ---------------------------------------------------------------------------
#define GEMM_SMEM 98304

template <int MODE>
__device__ __forceinline__ void gemm_tc_body(
    const __nv_bfloat16* __restrict__ Ap, const __nv_bfloat16* __restrict__ Wp,
    const float* __restrict__ bias, void* __restrict__ Cout, float oscale, char* smem)
{
    const uint32_t sb = smem_u32(smem);
    const int tid = threadIdx.x, lane = tid & 31, wid = tid >> 5;
    const int n0 = blockIdx.x * 64, m0 = blockIdx.y * 128;
    const char* Ab = (const char*)Ap;
    const char* Wb = (const char*)Wp;

    auto stage = [&](int t, uint32_t buf) {
        #pragma unroll
        for (int i = 0; i < 8; i++) {
            int g = i * 256 + tid;
            int blk = g >> 10, row = (g >> 3) & 127, ch = g & 7;
            CP16(sb + buf + blk * 16384 + row * 128 + ch * 16,
                 Ab + ((size_t)(t * 2 + blk) * M_ROWS + m0 + row) * 128 + ch * 16);
        }
        #pragma unroll
        for (int i = 0; i < 4; i++) {
            int g = i * 256 + tid;
            int blk = g >> 9, row = (g >> 3) & 63, ch = g & 7;
            CP16(sb + buf + 32768 + blk * 8192 + row * 128 + ch * 16,
                 Wb + ((size_t)(t * 2 + blk) * 256 + n0 + row) * 128 + ch * 16);
        }
        CP_COMMIT();
    };

    stage(0, 0);

    float c[8][4];
    #pragma unroll
    for (int i = 0; i < 8; i++)
        #pragma unroll
        for (int j = 0; j < 4; j++) c[i][j] = 0.f;

    const int m_off = (lane & 7) + ((lane >> 3) & 1) * 8;
    const int coff  = (lane >> 4) & 1;
    const int m = wid * 16 + m_off;
    const int kb_row = (lane & 7) + ((lane >> 4) & 1) * 8;
    const int kb_c   = (lane >> 3) & 1;

    for (int t = 0; t < 4; t++) {
        if (t < 3) { stage(t + 1, ((t + 1) & 1) * 49152); CPG_WAIT1(); }
        else       { CP_WAIT0(); }
        __syncthreads();

        const uint32_t abase = sb + (t & 1) * 49152;
        const uint32_t wbase = abase + 32768;

        #pragma unroll
        for (int k16 = 0; k16 < 4; k16++) {
            const int ablk = k16 >> 1;
            const int ch = 2 * (k16 & 1) + coff;
            const uint32_t arow = abase + ablk * 16384 + m * 128;
            uint32_t afh[4], afl[4];
            ldm_x4(afh, arow + (((ch)     ^ (m & 7)) << 4));
            ldm_x4(afl, arow + (((ch + 4) ^ (m & 7)) << 4));
            #pragma unroll
            for (int np = 0; np < 4; np++) {
                const int n = np * 16 + kb_row;
                const uint32_t wrow = wbase + ablk * 8192 + n * 128;
                const int wch = 2 * (k16 & 1) + kb_c;
                uint32_t bhf[4], blf[4];
                ldm_x4(bhf, wrow + (((wch)     ^ (n & 7)) << 4));
                mma_bf16(c[2 * np],     afh, bhf + 0);
                mma_bf16(c[2 * np + 1], afh, bhf + 2);
                mma_bf16(c[2 * np],     afl, bhf + 0);
                mma_bf16(c[2 * np + 1], afl, bhf + 2);
                ldm_x4(blf, wrow + (((wch + 4) ^ (n & 7)) << 4));
                mma_bf16(c[2 * np],     afh, blf + 0);
                mma_bf16(c[2 * np + 1], afh, blf + 2);
            }
        }
        __syncthreads();
    }

    const int r0 = m0 + wid * 16 + (lane >> 2);
    if (MODE == 0) {
        float* C = (float*)Cout;
        #pragma unroll
        for (int np = 0; np < 4; np++) {
            #pragma unroll
            for (int half = 0; half < 2; half++) {
                const int col = n0 + np * 16 + half * 8 + (lane & 3) * 2;
                const float b0 = bias[col], b1 = bias[col + 1];
                float* p0 = C + (size_t)r0 * DMODEL + col;
                *(float2*)p0 = make_float2(c[2 * np + half][0] + b0, c[2 * np + half][1] + b1);
                *(float2*)(p0 + 8 * DMODEL) = make_float2(c[2 * np + half][2] + b0, c[2 * np + half][3] + b1);
            }
        }
    } else {
        // fp16 attn image: row (b,h,s) -> 32 halves at ((b*8+h)*2048+s)*32,
        // halves index d ^ (((s>>1)&3)<<3). Note sw(s) == sw(s+8).
        uint32_t* P32 = (uint32_t*)Cout;
        const int bb = r0 >> 11, s = r0 & (S_LEN - 1);
        const int sw = ((s >> 1) & 3) << 3;
        #pragma unroll
        for (int np = 0; np < 4; np++) {
            #pragma unroll
            for (int half = 0; half < 2; half++) {
                const int col = n0 + np * 16 + half * 8 + (lane & 3) * 2;
                const int hh = col >> 5, d = col & 31;
                const float b0 = bias[col], b1 = bias[col + 1];
                const size_t base = ((size_t)(bb * 8 + hh) * S_LEN + s) * 32;
                uint32_t p01, p23;
                CVT_F16X2(p01, (c[2 * np + half][0] + b0) * oscale,
                               (c[2 * np + half][1] + b1) * oscale);
                CVT_F16X2(p23, (c[2 * np + half][2] + b0) * oscale,
                               (c[2 * np + half][3] + b1) * oscale);
                P32[(base + (d ^ sw)) >> 1]       = p01;   // row s
                P32[(base + 256 + (d ^ sw)) >> 1] = p23;   // row s+8
            }
        }
    }
}

__global__ __launch_bounds__(256, 2) void gemm_tc_qkv(
    const __nv_bfloat16* __restrict__ Aq, const __nv_bfloat16* __restrict__ Ak,
    const __nv_bfloat16* __restrict__ Av, const __nv_bfloat16* __restrict__ Wp,
    const float* __restrict__ bq, const float* __restrict__ bk, const float* __restrict__ bv,
    __half* __restrict__ Qp, __half* __restrict__ Kp, float* __restrict__ Vo)
{
    extern __shared__ char smem[];
    if (blockIdx.z == 0)
        gemm_tc_body<1>(Aq, Wp,                      bq, Qp, ATTN_SC, smem);
    else if (blockIdx.z == 1)
        gemm_tc_body<1>(Ak, Wp + (size_t)1 * 131072, bk, Kp, 1.0f,    smem);
    else
        gemm_tc_body<0>(Av, Wp + (size_t)2 * 131072, bv, Vo, 1.0f,    smem);
}

__global__ __launch_bounds__(256, 2) void gemm_tc_one(
    const __nv_bfloat16* __restrict__ Ap, const __nv_bfloat16* __restrict__ Wp,
    const float* __restrict__ bias, float* __restrict__ C)
{
    extern __shared__ char smem[];
    gemm_tc_body<0>(Ap, Wp, bias, C, 1.0f, smem);
}

// ---------------------------------------------------------------------------
// fp16 single-pass mma flash attention, 128-key iterations (2 x 64 subtiles).
// Q arrives pre-packed fp16 (SC folded) via cp.async — no convert stage.
// smem: KV double buffer [2][16KB] at 0 (K 8KB | V 8KB); Q fp16 8KB at 32KB.
// ---------------------------------------------------------------------------
#define SM_KV 0
#define SM_Q  32768
#define ATTN_SMEM 40960

__global__ __launch_bounds__(256, 2) void attn_mma_kernel(
    const __half* __restrict__ Qp, const __half* __restrict__ Kp,
    const __half* __restrict__ Vp, const unsigned* __restrict__ mbits)
{
    extern __shared__ char smem[];
    const uint32_t sb = smem_u32(smem);
    const int tid = threadIdx.x;
    const int lane = tid & 31, wid = tid >> 5;
    const int b = blockIdx.z, h = blockIdx.y;
    const int q0 = blockIdx.x * 128;
    const int bh = b * NHEADS + h;

    const char* ksrc = (const char*)(Kp + (size_t)bh * 65536);
    const char* vsrc = (const char*)(Vp + (size_t)bh * 65536);
    const char* qsrc = (const char*)(Qp + ((size_t)bh * S_LEN + q0) * 32);

    // ---- prefetch Q tile (8KB) + KV iteration 0 (16KB) ----
    {
        uint32_t dq = sb + SM_Q;
        CP16(dq + tid * 16,         qsrc + tid * 16);
        CP16(dq + (tid + 256) * 16, qsrc + (tid + 256) * 16);
        uint32_t d0 = sb + SM_KV;
        CP16(d0 + tid * 16,                ksrc + tid * 16);
        CP16(d0 + (tid + 256) * 16,        ksrc + (tid + 256) * 16);
        CP16(d0 + 8192 + tid * 16,         vsrc + tid * 16);
        CP16(d0 + 8192 + (tid + 256) * 16, vsrc + (tid + 256) * 16);
        CP_COMMIT();
    }
    CP_WAIT0();
    __syncthreads();

    // ---- Q A-fragments (fp16, single image) ----
    uint32_t qf[2][4];
    {
        const int m_off = (lane & 7) + ((lane >> 3) & 1) * 8;
        const int coff  = (lane >> 4) & 1;
        const int m = wid * 16 + m_off;
        const uint32_t qrow = sb + SM_Q + m * 64;
        const int swq = (m >> 1) & 3;
        #pragma unroll
        for (int k16 = 0; k16 < 2; k16++) {
            int ch = 2 * k16 + coff;
            ldm_x4(qf[k16], qrow + ((ch ^ swq) << 4));
        }
    }

    const int kb_row = (lane & 7) + ((lane >> 4) & 1) * 8;
    const int kb_c   = (lane >> 3) & 1;

    const unsigned* mb0 = mbits + (size_t)(b * S_LEN + q0 + wid * 16 + (lane >> 2)) * MWORDS;
    const unsigned* mb1 = mb0 + 8 * MWORDS;

    float l0 = 0.f, l1 = 0.f;
    float o[4][4];
    #pragma unroll
    for (int i = 0; i < 4; i++)
        #pragma unroll
        for (int j = 0; j < 4; j++) o[i][j] = 0.f;

    for (int it = 0; it < 16; it++) {
        if (it) { CP_WAIT0(); __syncthreads(); }

        // prefetch it+1 into the other slot (safe: slot last read at it-1)
        if (it < 15) {
            uint32_t d1 = sb + SM_KV + ((it + 1) & 1) * 16384;
            const char* ks = ksrc + (size_t)(it + 1) * 8192;
            const char* vs = vsrc + (size_t)(it + 1) * 8192;
            CP16(d1 + tid * 16,                ks + tid * 16);
            CP16(d1 + (tid + 256) * 16,        ks + (tid + 256) * 16);
            CP16(d1 + 8192 + tid * 16,         vs + tid * 16);
            CP16(d1 + 8192 + (tid + 256) * 16, vs + (tid + 256) * 16);
            CP_COMMIT();
        }

        const uint32_t slot = sb + SM_KV + (it & 1) * 16384;

        #pragma unroll
        for (int sub = 0; sub < 2; sub++) {
            const uint32_t kbase = slot + sub * 4096;
            const uint32_t vbase = slot + 8192 + sub * 4096;

            // ---- QK^T (fp16): 8 ldm + 16 mma ----
            float c[8][4];
            #pragma unroll
            for (int i = 0; i < 8; i++)
                #pragma unroll
                for (int j = 0; j < 4; j++) c[i][j] = 0.f;

            #pragma unroll
            for (int k16 = 0; k16 < 2; k16++) {
                #pragma unroll
                for (int np = 0; np < 4; np++) {
                    const int key = np * 16 + kb_row;
                    const int ch  = 2 * k16 + kb_c;
                    uint32_t bf[4];
                    ldm_x4(bf, kbase + key * 64 + ((ch ^ ((key >> 1) & 3)) << 4));
                    mma_f16(c[2 * np],     qf[k16], bf + 0);
                    mma_f16(c[2 * np + 1], qf[k16], bf + 2);
                }
            }

            // ---- softmax -> P fp16 fragments ----
            const uint64_t mw0 = *(const uint64_t*)(mb0 + it * 4 + sub * 2);
            const uint64_t mw1 = *(const uint64_t*)(mb1 + it * 4 + sub * 2);
            uint32_t ap[4][4];
            #pragma unroll
            for (int jj = 0; jj < 4; jj++) {
                #pragma unroll
                for (int half = 0; half < 2; half++) {
                    const int j = 2 * jj + half;
                    const int colb = j * 8 + (lane & 3) * 2;
                    float p0 = ((mw0 >> colb)       & 1) ? ex2(c[j][0]) : 0.f;
                    float p1 = ((mw0 >> (colb + 1)) & 1) ? ex2(c[j][1]) : 0.f;
                    float p2 = ((mw1 >> colb)       & 1) ? ex2(c[j][2]) : 0.f;
                    float p3 = ((mw1 >> (colb + 1)) & 1) ? ex2(c[j][3]) : 0.f;
                    l0 += p0 + p1; l1 += p2 + p3;
                    CVT_F16X2(ap[jj][half * 2],     p0, p1);
                    CVT_F16X2(ap[jj][half * 2 + 1], p2, p3);
                }
            }

            // ---- PV (fp16): 8 ldm + 16 mma ----
            #pragma unroll
            for (int k16 = 0; k16 < 4; k16++) {
                #pragma unroll
                for (int np = 0; np < 2; np++) {
                    const int d  = np * 16 + kb_row;
                    const int ch = 2 * k16 + kb_c;
                    uint32_t bv[4];
                    ldm_x4(bv, vbase + d * 128 + ((ch ^ (d & 7)) << 4));
                    mma_f16(o[2 * np],     ap[k16], bv + 0);
                    mma_f16(o[2 * np + 1], ap[k16], bv + 2);
                }
            }
        }
    }

    // ---- finalize: normalize and write packed bf16 hi/lo GEMM-A format ----
    l0 += __shfl_xor_sync(0xffffffffu, l0, 1);
    l0 += __shfl_xor_sync(0xffffffffu, l0, 2);
    l1 += __shfl_xor_sync(0xffffffffu, l1, 1);
    l1 += __shfl_xor_sync(0xffffffffu, l1, 2);
    const float inv0 = 1.f / l0, inv1 = 1.f / l1;

    const int r0g = q0 + wid * 16 + (lane >> 2);
    const int r1g = r0g + 8;
    uint32_t* Op32 = (uint32_t*)g_Op;
    const size_t base0 = ((size_t)h * M_ROWS + b * S_LEN + r0g) * 32;
    const size_t base1 = ((size_t)h * M_ROWS + b * S_LEN + r1g) * 32;
    const int sw0 = (r0g & 7) << 3;
    const int sw1 = (r1g & 7) << 3;
    #pragma unroll
    for (int j = 0; j < 4; j++) {
        const int d = j * 8 + (lane & 3) * 2;
        float v0 = o[j][0] * inv0, v1 = o[j][1] * inv0;
        float v2 = o[j][2] * inv1, v3 = o[j][3] * inv1;
        uint32_t h01, h23;
        CVT_BF16X2(h01, v0, v1);
        CVT_BF16X2(h23, v2, v3);
        float r0l = v0 - __uint_as_float(h01 << 16);
        float r1l = v1 - __uint_as_float(h01 & 0xffff0000u);
        float r2l = v2 - __uint_as_float(h23 << 16);
        float r3l = v3 - __uint_as_float(h23 & 0xffff0000u);
        uint32_t l01, l23;
        CVT_BF16X2(l01, r0l, r1l);
        CVT_BF16X2(l23, r2l, r3l);
        Op32[base0 + (((d)      ^ sw0) >> 1)] = h01;
        Op32[base0 + (((32 + d) ^ sw0) >> 1)] = l01;
        Op32[base1 + (((d)      ^ sw1) >> 1)] = h23;
        Op32[base1 + (((32 + d) ^ sw1) >> 1)] = l23;
    }
}

// ---------------------------------------------------------------------------
// Launch
// ---------------------------------------------------------------------------
extern "C" void kernel_launch(void* const* d_in, const int* in_sizes, int n_in,
                              void* d_out, int out_size)
{
    const float* query = (const float*)d_in[0];
    const float* key   = (const float*)d_in[1];
    const float* value = (const float*)d_in[2];
    const int*   mask  = (const int*)  d_in[3];
    const float* Wq = (const float*)d_in[4];
    const float* bq = (const float*)d_in[5];
    const float* Wk = (const float*)d_in[6];
    const float* bk = (const float*)d_in[7];
    const float* Wv = (const float*)d_in[8];
    const float* bv = (const float*)d_in[9];
    const float* Wo = (const float*)d_in[10];
    const float* bo = (const float*)d_in[11];
    float* out = (float*)d_out;

    float* Vb;
    unsigned* MBp;
    __half *Qpp, *Kpp, *Vpp;
    __nv_bfloat16 *Aq, *Ak, *Av, *Op, *Wp;
    cudaGetSymbolAddress((void**)&Vb, g_V);
    cudaGetSymbolAddress((void**)&MBp, g_MB);
    cudaGetSymbolAddress((void**)&Qpp, g_Qp16);
    cudaGetSymbolAddress((void**)&Kpp, g_Kp16);
    cudaGetSymbolAddress((void**)&Vpp, g_Vp16);
    cudaGetSymbolAddress((void**)&Aq, g_Aq);
    cudaGetSymbolAddress((void**)&Ak, g_Ak);
    cudaGetSymbolAddress((void**)&Av, g_Av);
    cudaGetSymbolAddress((void**)&Op, g_Op);
    cudaGetSymbolAddress((void**)&Wp, g_Wp);

    cudaFuncSetAttribute(attn_mma_kernel, cudaFuncAttributeMaxDynamicSharedMemorySize, ATTN_SMEM);
    cudaFuncSetAttribute(gemm_tc_qkv, cudaFuncAttributeMaxDynamicSharedMemorySize, GEMM_SMEM);
    cudaFuncSetAttribute(gemm_tc_one, cudaFuncAttributeMaxDynamicSharedMemorySize, GEMM_SMEM);

    pack_mask_kernel<<<(BATCH * S_LEN * S_LEN) / 8 / 256, 256>>>(
        (const int4*)mask, (unsigned char*)MBp);
    pack_w_kernel<<<(4 * 8 * 256 * 64) / 256, 256>>>(Wq, Wk, Wv, Wo, Wp);
    pack_a3_kernel<<<dim3((8 * M_ROWS * 8) / 256, 3), 256>>>(query, key, value, Aq, Ak, Av);

    gemm_tc_qkv<<<dim3(4, 64, 3), 256, GEMM_SMEM>>>(Aq, Ak, Av, Wp,
                                                    bq, bk, bv, Qpp, Kpp, Vb);

    pack_v16_kernel<<<(NBH * 32 * 32 * 64) / 256, 256>>>(Vb, Vpp);

    dim3 attn_grid(S_LEN / 128, NHEADS, BATCH);   // (16, 8, 4)
    attn_mma_kernel<<<attn_grid, 256, ATTN_SMEM>>>(Qpp, Kpp, Vpp, MBp);

    gemm_tc_one<<<dim3(4, 64), 256, GEMM_SMEM>>>(Op, Wp + (size_t)3 * 131072, bo, out);
}